// round 2
// baseline (speedup 1.0000x reference)
#include <cuda_runtime.h>
#include <math.h>

#define BB   1024
#define NN   128
#define EE   1024
#define HH   128
#define LL   4
#define INDIM 16
#define DIN  19
#define EDIM 4
#define NH   (NN*HH)      // 16384
#define HSQ  (HH*HH)      // 16384

// ---------------- device scratch (no runtime allocation allowed) ----------------
__device__ float g_mag[(size_t)BB*NH];
__device__ float g_ph [(size_t)BB*NH];
__device__ float g_q  [(size_t)BB*NH];
__device__ float g_k  [(size_t)BB*NH];
__device__ float g_vm [(size_t)BB*NH];
__device__ float g_vp [(size_t)BB*NH];

// ---------------- K0: complex embedding ----------------
// grid = B, block = 128 (thread = hidden index h)
__global__ void k_embed(const float* __restrict__ at, const float* __restrict__ sph,
                        const float* __restrict__ Wm, const float* __restrict__ bm,
                        const float* __restrict__ Wp, const float* __restrict__ bp)
{
    int b = blockIdx.x, t = threadIdx.x;
    __shared__ float sx[NN][20];
    for (int i = t; i < NN*DIN; i += blockDim.x) {
        int n = i / DIN, d = i % DIN;
        sx[n][d] = (d < INDIM) ? at[((size_t)b*NN + n)*INDIM + d]
                               : sph[((size_t)b*NN + n)*3 + (d - INDIM)];
    }
    __syncthreads();
    float wm[DIN], wp[DIN];
#pragma unroll
    for (int d = 0; d < DIN; d++) { wm[d] = Wm[d*HH + t]; wp[d] = Wp[d*HH + t]; }
    float bmv = bm[t], bpv = bp[t];
    size_t base = (size_t)b*NH;
    for (int n = 0; n < NN; n++) {
        float am = bmv, ap = bpv;
#pragma unroll
        for (int d = 0; d < DIN; d++) { float x = sx[n][d]; am = fmaf(x, wm[d], am); ap = fmaf(x, wp[d], ap); }
        g_mag[base + (size_t)n*HH + t] = am;
        g_ph [base + (size_t)n*HH + t] = ap;
    }
}

// ---------------- K1: generic projection SGEMM ----------------
// C[M,128] = A[M,128] @ W[128,128] + bias, M = B*N, BM=64, BN=128, BK=16
__global__ __launch_bounds__(256) void k_gemm(const float* __restrict__ A,
                                              const float* __restrict__ W,
                                              const float* __restrict__ bias,
                                              float* __restrict__ C)
{
    __shared__ float sA[16*68];    // transposed A tile: sA[k][row], stride 68
    __shared__ float sW[16*132];   // W tile: sW[k][col], stride 132

    int tid = threadIdx.x;
    int tx = tid & 15, ty = tid >> 4;
    int m0 = blockIdx.x * 64;
    int lr = tid >> 2, lq = tid & 3;     // A-tile loader: row, quad-of-4-cols

    float acc[4][8];
#pragma unroll
    for (int i = 0; i < 4; i++)
#pragma unroll
        for (int j = 0; j < 8; j++) acc[i][j] = 0.f;

    for (int k0 = 0; k0 < HH; k0 += 16) {
        float4 av = *(const float4*)(A + (size_t)(m0 + lr)*HH + k0 + 4*lq);
        int i0 = tid, i1 = tid + 256;
        float4 wv0 = *(const float4*)(W + (size_t)(k0 + (i0 >> 5))*HH + 4*(i0 & 31));
        float4 wv1 = *(const float4*)(W + (size_t)(k0 + (i1 >> 5))*HH + 4*(i1 & 31));
        __syncthreads();
        sA[(4*lq + 0)*68 + lr] = av.x;
        sA[(4*lq + 1)*68 + lr] = av.y;
        sA[(4*lq + 2)*68 + lr] = av.z;
        sA[(4*lq + 3)*68 + lr] = av.w;
        *(float4*)(sW + (i0 >> 5)*132 + 4*(i0 & 31)) = wv0;
        *(float4*)(sW + (i1 >> 5)*132 + 4*(i1 & 31)) = wv1;
        __syncthreads();
#pragma unroll
        for (int kk = 0; kk < 16; kk++) {
            float4 a4 = *(const float4*)(sA + kk*68 + 4*ty);
            float4 b0 = *(const float4*)(sW + kk*132 + 8*tx);
            float4 b1 = *(const float4*)(sW + kk*132 + 8*tx + 4);
            float a[4] = {a4.x, a4.y, a4.z, a4.w};
            float bb[8] = {b0.x, b0.y, b0.z, b0.w, b1.x, b1.y, b1.z, b1.w};
#pragma unroll
            for (int i = 0; i < 4; i++)
#pragma unroll
                for (int j = 0; j < 8; j++) acc[i][j] = fmaf(a[i], bb[j], acc[i][j]);
        }
    }

    float bv[8];
#pragma unroll
    for (int j = 0; j < 8; j++) bv[j] = bias[8*tx + j];
#pragma unroll
    for (int i = 0; i < 4; i++) {
        size_t row = (size_t)(m0 + 4*ty + i);
        float4 o0 = make_float4(acc[i][0] + bv[0], acc[i][1] + bv[1], acc[i][2] + bv[2], acc[i][3] + bv[3]);
        float4 o1 = make_float4(acc[i][4] + bv[4], acc[i][5] + bv[5], acc[i][6] + bv[6], acc[i][7] + bv[7]);
        *(float4*)(C + row*HH + 8*tx)     = o0;
        *(float4*)(C + row*HH + 8*tx + 4) = o1;
    }
}

// ---------------- K2: per-molecule attention layer ----------------
// grid = B, block = 256, dynamic smem = 3 * 128*132 floats
#define SSTR 132
__global__ __launch_bounds__(256) void k_attn(
    const int* __restrict__ ei, const float* __restrict__ ea,
    const float* __restrict__ We, const float* __restrict__ be,
    const float* __restrict__ ds,
    const float* __restrict__ lng, const float* __restrict__ lnb,
    int l)
{
    extern __shared__ float sm[];
    float* SQ = sm;
    float* SK = sm + NN*SSTR;
    float* SS = sm + 2*NN*SSTR;

    int b = blockIdx.x, tid = threadIdx.x;
    int tx = tid & 15, ty = tid >> 4;
    size_t base = (size_t)b*NH;
    const float* qp  = g_q  + base;
    const float* kp  = g_k  + base;
    const float* vmp = g_vm + base;
    const float* vpp = g_vp + base;

    // load Q, K (coalesced), zero SS
    for (int i = tid; i < 4096; i += 256) {
        int r = i >> 5, c = (i & 31) * 4;
        *(float4*)(SQ + r*SSTR + c) = *(const float4*)(qp + (size_t)r*HH + c);
        *(float4*)(SK + r*SSTR + c) = *(const float4*)(kp + (size_t)r*HH + c);
    }
    for (int i = tid; i < NN*SSTR/4; i += 256) ((float4*)SS)[i] = make_float4(0.f, 0.f, 0.f, 0.f);
    __syncthreads();

    // edge bias scatter
    float w0 = We[l*4+0], w1 = We[l*4+1], w2 = We[l*4+2], w3 = We[l*4+3];
    float beL = be[l], dsL = ds[l];
    for (int e = tid; e < EE; e += 256) {
        int i0 = ei[(size_t)b*2*EE + e];
        int j0 = ei[(size_t)b*2*EE + EE + e];
        const float* a = ea + ((size_t)b*EE + e)*EDIM;
        float v = fmaf(a[0], w0, fmaf(a[1], w1, fmaf(a[2], w2, fmaf(a[3], w3, beL)))) + dsL*a[0];
        atomicAdd(&SS[i0*SSTR + j0], v);
    }
    __syncthreads();

    // scores = q @ k^T * scale + bias
    {
        float acc[8][8];
#pragma unroll
        for (int i = 0; i < 8; i++)
#pragma unroll
            for (int j = 0; j < 8; j++) acc[i][j] = 0.f;
        for (int h = 0; h < HH; h++) {
            float a[8], bb[8];
#pragma unroll
            for (int ii = 0; ii < 8; ii++) a[ii]  = SQ[(ty + 16*ii)*SSTR + h];
#pragma unroll
            for (int jj = 0; jj < 8; jj++) bb[jj] = SK[(tx + 16*jj)*SSTR + h];
#pragma unroll
            for (int ii = 0; ii < 8; ii++)
#pragma unroll
                for (int jj = 0; jj < 8; jj++) acc[ii][jj] = fmaf(a[ii], bb[jj], acc[ii][jj]);
        }
        const float scale = 0.08838834764831845f;  // 1/sqrt(128)
#pragma unroll
        for (int ii = 0; ii < 8; ii++)
#pragma unroll
            for (int jj = 0; jj < 8; jj++) {
                int r = ty + 16*ii, c = tx + 16*jj;
                SS[r*SSTR + c] = fmaf(acc[ii][jj], scale, SS[r*SSTR + c]);
            }
    }
    __syncthreads();

    // softmax per row
    if (tid < NN) {
        float* row = SS + tid*SSTR;
        float m = -1e30f;
        for (int j = 0; j < NN; j++) m = fmaxf(m, row[j]);
        float s = 0.f;
        for (int j = 0; j < NN; j++) { float ev = __expf(row[j] - m); row[j] = ev; s += ev; }
        float inv = 1.f / s;
        for (int j = 0; j < NN; j++) row[j] *= inv;
    }
    __syncthreads();

    // load vm -> SK, mag residual -> SQ
    for (int i = tid; i < 4096; i += 256) {
        int r = i >> 5, c = (i & 31) * 4;
        *(float4*)(SK + r*SSTR + c) = *(const float4*)(vmp + (size_t)r*HH + c);
        *(float4*)(SQ + r*SSTR + c) = *(const float4*)(g_mag + base + (size_t)r*HH + c);
    }
    __syncthreads();

    // new_mag = attn @ vm + mag  (accumulate into SQ)
    {
        float acc[8][8];
#pragma unroll
        for (int i = 0; i < 8; i++)
#pragma unroll
            for (int j = 0; j < 8; j++) acc[i][j] = 0.f;
        for (int jx = 0; jx < NN; jx++) {
            float a[8], bb[8];
#pragma unroll
            for (int ii = 0; ii < 8; ii++) a[ii]  = SS[(ty + 16*ii)*SSTR + jx];
#pragma unroll
            for (int jj = 0; jj < 8; jj++) bb[jj] = SK[jx*SSTR + tx + 16*jj];
#pragma unroll
            for (int ii = 0; ii < 8; ii++)
#pragma unroll
                for (int jj = 0; jj < 8; jj++) acc[ii][jj] = fmaf(a[ii], bb[jj], acc[ii][jj]);
        }
#pragma unroll
        for (int ii = 0; ii < 8; ii++)
#pragma unroll
            for (int jj = 0; jj < 8; jj++) {
                int r = ty + 16*ii, c = tx + 16*jj;
                SQ[r*SSTR + c] += acc[ii][jj];
            }
    }
    __syncthreads();

    // LayerNorm rows of SQ
    if (tid < NN) {
        float* row = SQ + tid*SSTR;
        float mu = 0.f;
        for (int j = 0; j < NN; j++) mu += row[j];
        mu *= (1.f/128.f);
        float var = 0.f;
        for (int j = 0; j < NN; j++) { float d = row[j] - mu; var = fmaf(d, d, var); }
        var *= (1.f/128.f);
        float rs = rsqrtf(var + 1e-5f);
        for (int j = 0; j < NN; j++)
            row[j] = fmaf(lng[l*HH + j], (row[j] - mu)*rs, lnb[l*HH + j]);
    }
    __syncthreads();

    // write new mag (coalesced)
    for (int i = tid; i < 4096; i += 256) {
        int r = i >> 5, c = (i & 31) * 4;
        *(float4*)(g_mag + base + (size_t)r*HH + c) = *(const float4*)(SQ + r*SSTR + c);
    }
    __syncthreads();

    // load vp -> SK, ph residual -> SQ
    for (int i = tid; i < 4096; i += 256) {
        int r = i >> 5, c = (i & 31) * 4;
        *(float4*)(SK + r*SSTR + c) = *(const float4*)(vpp + (size_t)r*HH + c);
        *(float4*)(SQ + r*SSTR + c) = *(const float4*)(g_ph + base + (size_t)r*HH + c);
    }
    __syncthreads();

    // new_ph = attn @ vp + ph
    {
        float acc[8][8];
#pragma unroll
        for (int i = 0; i < 8; i++)
#pragma unroll
            for (int j = 0; j < 8; j++) acc[i][j] = 0.f;
        for (int jx = 0; jx < NN; jx++) {
            float a[8], bb[8];
#pragma unroll
            for (int ii = 0; ii < 8; ii++) a[ii]  = SS[(ty + 16*ii)*SSTR + jx];
#pragma unroll
            for (int jj = 0; jj < 8; jj++) bb[jj] = SK[jx*SSTR + tx + 16*jj];
#pragma unroll
            for (int ii = 0; ii < 8; ii++)
#pragma unroll
                for (int jj = 0; jj < 8; jj++) acc[ii][jj] = fmaf(a[ii], bb[jj], acc[ii][jj]);
        }
#pragma unroll
        for (int ii = 0; ii < 8; ii++)
#pragma unroll
            for (int jj = 0; jj < 8; jj++) {
                int r = ty + 16*ii, c = tx + 16*jj;
                SQ[r*SSTR + c] += acc[ii][jj];
            }
    }
    __syncthreads();

    // write new ph (coalesced)
    for (int i = tid; i < 4096; i += 256) {
        int r = i >> 5, c = (i & 31) * 4;
        *(float4*)(g_ph + base + (size_t)r*HH + c) = *(const float4*)(SQ + r*SSTR + c);
    }
}

// ---------------- K3: real projection + pooling + MLP head ----------------
// grid = B, block = 128. Pooling commutes with the linear rp projection:
// sum_n atom_repr = (sum_n RI) @ rp_W + N*rp_b ; mean = sum/N.
__global__ void k_head(const float* __restrict__ rpW, const float* __restrict__ rpb,
                       const float* __restrict__ h1W, const float* __restrict__ h1b,
                       const float* __restrict__ h2W, const float* __restrict__ h2b,
                       float* __restrict__ out)
{
    int b = blockIdx.x, t = threadIdx.x;
    __shared__ float sS[2*HH];
    __shared__ float sp[2*HH];
    __shared__ float sr[HH];
    size_t base = (size_t)b*NH;

    float ac = 0.f, as = 0.f;
    for (int n = 0; n < NN; n++) {
        float m = g_mag[base + (size_t)n*HH + t];
        float p = g_ph [base + (size_t)n*HH + t];
        float si, co;
        sincosf(p, &si, &co);
        ac = fmaf(m, co, ac);
        as = fmaf(m, si, as);
    }
    sS[t] = ac; sS[HH + t] = as;
    __syncthreads();

    float d = 0.f;
    for (int c = 0; c < 2*HH; c++) d = fmaf(sS[c], rpW[(size_t)c*HH + t], d);
    float sumr = d + 128.f * rpb[t];
    sp[t]      = sumr * (1.f/128.f);  // mean-pool part
    sp[HH + t] = sumr;                // sum-pool part
    __syncthreads();

    float hv = h1b[t];
    for (int c = 0; c < 2*HH; c++) hv = fmaf(sp[c], h1W[(size_t)c*HH + t], hv);
    hv = hv / (1.f + expf(-hv));      // SiLU
    sr[t] = hv * h2W[t];
    __syncthreads();

    for (int s = 64; s >= 1; s >>= 1) {
        if (t < s) sr[t] += sr[t + s];
        __syncthreads();
    }
    if (t == 0) out[b] = sr[0] + h2b[0];
}

// ---------------- launch ----------------
extern "C" void kernel_launch(void* const* d_in, const int* in_sizes, int n_in,
                              void* d_out, int out_size)
{
    const float* at   = (const float*)d_in[0];
    const float* sph  = (const float*)d_in[1];
    const int*   ei   = (const int*)  d_in[2];
    const float* ea   = (const float*)d_in[3];
    const float* Wm   = (const float*)d_in[4];
    const float* bm   = (const float*)d_in[5];
    const float* Wp   = (const float*)d_in[6];
    const float* bp   = (const float*)d_in[7];
    const float* Wq   = (const float*)d_in[8];
    const float* bq   = (const float*)d_in[9];
    const float* Wk   = (const float*)d_in[10];
    const float* bk   = (const float*)d_in[11];
    const float* Wvm  = (const float*)d_in[12];
    const float* bvm  = (const float*)d_in[13];
    const float* Wvp  = (const float*)d_in[14];
    const float* bvp  = (const float*)d_in[15];
    const float* We   = (const float*)d_in[16];
    const float* be   = (const float*)d_in[17];
    const float* ds   = (const float*)d_in[18];
    const float* lng  = (const float*)d_in[19];
    const float* lnb  = (const float*)d_in[20];
    const float* rpW  = (const float*)d_in[21];
    const float* rpb  = (const float*)d_in[22];
    const float* h1W  = (const float*)d_in[23];
    const float* h1b  = (const float*)d_in[24];
    const float* h2W  = (const float*)d_in[25];
    const float* h2b  = (const float*)d_in[26];
    float* out = (float*)d_out;

    void *p_mag, *p_ph, *p_q, *p_k, *p_vm, *p_vp;
    cudaGetSymbolAddress(&p_mag, g_mag);
    cudaGetSymbolAddress(&p_ph,  g_ph);
    cudaGetSymbolAddress(&p_q,   g_q);
    cudaGetSymbolAddress(&p_k,   g_k);
    cudaGetSymbolAddress(&p_vm,  g_vm);
    cudaGetSymbolAddress(&p_vp,  g_vp);

    size_t attn_smem = (size_t)3 * NN * SSTR * sizeof(float);  // 202752 B
    cudaFuncSetAttribute(k_attn, cudaFuncAttributeMaxDynamicSharedMemorySize, (int)attn_smem);

    k_embed<<<BB, 128>>>(at, sph, Wm, bm, Wp, bp);

    int gblk = (BB * NN) / 64;  // 2048
    for (int l = 0; l < LL; l++) {
        k_gemm<<<gblk, 256>>>((const float*)p_mag, Wq + (size_t)l*HSQ, bq + (size_t)l*HH, (float*)p_q);
        k_gemm<<<gblk, 256>>>((const float*)p_mag, Wk + (size_t)l*HSQ, bk + (size_t)l*HH, (float*)p_k);
        k_gemm<<<gblk, 256>>>((const float*)p_mag, Wvm + (size_t)l*HSQ, bvm + (size_t)l*HH, (float*)p_vm);
        k_gemm<<<gblk, 256>>>((const float*)p_ph,  Wvp + (size_t)l*HSQ, bvp + (size_t)l*HH, (float*)p_vp);
        k_attn<<<BB, 256, attn_smem>>>(ei, ea, We, be, ds, lng, lnb, l);
    }

    k_head<<<BB, 128>>>(rpW, rpb, h1W, h1b, h2W, h2b, out);
}

// round 3
// speedup vs baseline: 1.2628x; 1.2628x over previous
#include <cuda_runtime.h>
#include <math.h>

#define BB   1024
#define NN   128
#define EE   1024
#define HH   128
#define LL   4
#define INDIM 16
#define DIN  19
#define EDIM 4
#define NH   (NN*HH)      // 16384
#define HSQ  (HH*HH)      // 16384
#define SSTR 132

typedef unsigned long long u64;

__device__ __forceinline__ u64 pk2(float x, float y) {
    u64 r; asm("mov.b64 %0, {%1,%2};" : "=l"(r) : "f"(x), "f"(y)); return r;
}
__device__ __forceinline__ void up2(u64 v, float& x, float& y) {
    asm("mov.b64 {%0,%1}, %2;" : "=f"(x), "=f"(y) : "l"(v));
}
#define FMA2(c, a, b) asm("fma.rn.f32x2 %0, %1, %2, %0;" : "+l"(c) : "l"(a), "l"(b))

// ---------------- device scratch ----------------
__device__ float g_mag[(size_t)BB*NH];
__device__ float g_ph [(size_t)BB*NH];
__device__ float g_q  [(size_t)BB*NH];
__device__ float g_k  [(size_t)BB*NH];
__device__ float g_vm [(size_t)BB*NH];
__device__ float g_vp [(size_t)BB*NH];

// ---------------- K0: complex embedding ----------------
__global__ void k_embed(const float* __restrict__ at, const float* __restrict__ sph,
                        const float* __restrict__ Wm, const float* __restrict__ bm,
                        const float* __restrict__ Wp, const float* __restrict__ bp)
{
    int b = blockIdx.x, t = threadIdx.x;
    __shared__ float sx[NN][20];
    for (int i = t; i < NN*DIN; i += blockDim.x) {
        int n = i / DIN, d = i % DIN;
        sx[n][d] = (d < INDIM) ? at[((size_t)b*NN + n)*INDIM + d]
                               : sph[((size_t)b*NN + n)*3 + (d - INDIM)];
    }
    __syncthreads();
    float wm[DIN], wp[DIN];
#pragma unroll
    for (int d = 0; d < DIN; d++) { wm[d] = Wm[d*HH + t]; wp[d] = Wp[d*HH + t]; }
    float bmv = bm[t], bpv = bp[t];
    size_t base = (size_t)b*NH;
    for (int n = 0; n < NN; n++) {
        float am = bmv, ap = bpv;
#pragma unroll
        for (int d = 0; d < DIN; d++) { float x = sx[n][d]; am = fmaf(x, wm[d], am); ap = fmaf(x, wp[d], ap); }
        g_mag[base + (size_t)n*HH + t] = am;
        g_ph [base + (size_t)n*HH + t] = ap;
    }
}

// ---------------- K1: fused projection GEMM (all 4 per layer) ----------------
// grid = (1024, 4): y picks {q,k,vm,vp}. BM=128, BN=128, BK=16, 256 thr, 8x8 tile, f32x2.
__global__ __launch_bounds__(256) void k_proj(
    const float* __restrict__ Am, const float* __restrict__ Ap,
    const float* __restrict__ Wq, const float* __restrict__ bq,
    const float* __restrict__ Wk, const float* __restrict__ bk,
    const float* __restrict__ Wvm, const float* __restrict__ bvm,
    const float* __restrict__ Wvp, const float* __restrict__ bvp,
    float* __restrict__ Cq, float* __restrict__ Ck,
    float* __restrict__ Cvm, float* __restrict__ Cvp, int l)
{
    int p = blockIdx.y;
    const float* A; const float* W; const float* bias; float* C;
    if      (p == 0) { A = Am; W = Wq  + (size_t)l*HSQ; bias = bq  + l*HH; C = Cq;  }
    else if (p == 1) { A = Am; W = Wk  + (size_t)l*HSQ; bias = bk  + l*HH; C = Ck;  }
    else if (p == 2) { A = Am; W = Wvm + (size_t)l*HSQ; bias = bvm + l*HH; C = Cvm; }
    else             { A = Ap; W = Wvp + (size_t)l*HSQ; bias = bvp + l*HH; C = Cvp; }

    __shared__ float sA[16*SSTR];   // transposed: sA[k][row]
    __shared__ float sW[16*SSTR];   // row-major:  sW[k][col]

    int tid = threadIdx.x;
    int tx = tid & 15, ty = tid >> 4;
    size_t m0 = (size_t)blockIdx.x * 128;

    int ar = tid >> 1, aq = tid & 1;   // A loader: row, which 8-col half

    u64 acc[8][4];
#pragma unroll
    for (int i = 0; i < 8; i++)
#pragma unroll
        for (int j = 0; j < 4; j++) acc[i][j] = 0ull;

    for (int k0 = 0; k0 < HH; k0 += 16) {
        float4 a0 = *(const float4*)(A + (m0 + ar)*HH + k0 + 8*aq);
        float4 a1 = *(const float4*)(A + (m0 + ar)*HH + k0 + 8*aq + 4);
        float4 w0 = *(const float4*)(W + (size_t)(k0 + ty)*HH + 8*tx);
        float4 w1 = *(const float4*)(W + (size_t)(k0 + ty)*HH + 8*tx + 4);
        __syncthreads();
        sA[(8*aq + 0)*SSTR + ar] = a0.x; sA[(8*aq + 1)*SSTR + ar] = a0.y;
        sA[(8*aq + 2)*SSTR + ar] = a0.z; sA[(8*aq + 3)*SSTR + ar] = a0.w;
        sA[(8*aq + 4)*SSTR + ar] = a1.x; sA[(8*aq + 5)*SSTR + ar] = a1.y;
        sA[(8*aq + 6)*SSTR + ar] = a1.z; sA[(8*aq + 7)*SSTR + ar] = a1.w;
        *(float4*)(sW + ty*SSTR + 8*tx)     = w0;
        *(float4*)(sW + ty*SSTR + 8*tx + 4) = w1;
        __syncthreads();
#pragma unroll
        for (int kk = 0; kk < 16; kk++) {
            float4 av0 = *(const float4*)(sA + kk*SSTR + 8*ty);
            float4 av1 = *(const float4*)(sA + kk*SSTR + 8*ty + 4);
            u64 ad[8];
            ad[0] = pk2(av0.x, av0.x); ad[1] = pk2(av0.y, av0.y);
            ad[2] = pk2(av0.z, av0.z); ad[3] = pk2(av0.w, av0.w);
            ad[4] = pk2(av1.x, av1.x); ad[5] = pk2(av1.y, av1.y);
            ad[6] = pk2(av1.z, av1.z); ad[7] = pk2(av1.w, av1.w);
            ulonglong2 bv0 = *(const ulonglong2*)(sW + kk*SSTR + 8*tx);
            ulonglong2 bv1 = *(const ulonglong2*)(sW + kk*SSTR + 8*tx + 4);
            u64 bp_[4] = {bv0.x, bv0.y, bv1.x, bv1.y};
#pragma unroll
            for (int i = 0; i < 8; i++)
#pragma unroll
                for (int j = 0; j < 4; j++) FMA2(acc[i][j], ad[i], bp_[j]);
        }
    }

    float4 bb0 = *(const float4*)(bias + 8*tx);
    float4 bb1 = *(const float4*)(bias + 8*tx + 4);
    float bvv[8] = {bb0.x, bb0.y, bb0.z, bb0.w, bb1.x, bb1.y, bb1.z, bb1.w};
#pragma unroll
    for (int i = 0; i < 8; i++) {
        float o[8];
#pragma unroll
        for (int j = 0; j < 4; j++) { up2(acc[i][j], o[2*j], o[2*j+1]); }
#pragma unroll
        for (int j = 0; j < 8; j++) o[j] += bvv[j];
        size_t row = m0 + 8*ty + i;
        *(float4*)(C + row*HH + 8*tx)     = make_float4(o[0], o[1], o[2], o[3]);
        *(float4*)(C + row*HH + 8*tx + 4) = make_float4(o[4], o[5], o[6], o[7]);
    }
}

// ---------------- K2: per-molecule attention layer ----------------
__global__ __launch_bounds__(256) void k_attn(
    const int* __restrict__ ei, const float* __restrict__ ea,
    const float* __restrict__ We, const float* __restrict__ be,
    const float* __restrict__ ds,
    const float* __restrict__ lng, const float* __restrict__ lnb,
    int l)
{
    extern __shared__ float sm[];
    float* SA = sm;                 // Q, then residual
    float* SB = sm + NN*SSTR;       // K, then VM, then VP
    float* SS = sm + 2*NN*SSTR;     // scores

    int b = blockIdx.x, tid = threadIdx.x;
    int tx = tid & 15, ty = tid >> 4;
    size_t base = (size_t)b*NH;

    // ---- load Q, K row-major; zero SS ----
    for (int i = tid; i < 4096; i += 256) {
        int r = i >> 5, c = (i & 31) * 4;
        *(float4*)(SA + r*SSTR + c) = *(const float4*)(g_q + base + (size_t)r*HH + c);
        *(float4*)(SB + r*SSTR + c) = *(const float4*)(g_k + base + (size_t)r*HH + c);
    }
    for (int i = tid; i < NN*SSTR/4; i += 256) ((float4*)SS)[i] = make_float4(0.f, 0.f, 0.f, 0.f);
    __syncthreads();

    // ---- edge bias scatter ----
    {
        float w0 = We[l*4+0], w1 = We[l*4+1], w2 = We[l*4+2], w3 = We[l*4+3];
        float beL = be[l], dsL = ds[l];
        for (int e = tid; e < EE; e += 256) {
            int i0 = ei[(size_t)b*2*EE + e];
            int j0 = ei[(size_t)b*2*EE + EE + e];
            const float* a = ea + ((size_t)b*EE + e)*EDIM;
            float v = fmaf(a[0], w0, fmaf(a[1], w1, fmaf(a[2], w2, fmaf(a[3], w3, beL)))) + dsL*a[0];
            atomicAdd(&SS[i0*SSTR + j0], v);
        }
    }
    __syncthreads();

    // ---- scores = Q @ K^T (h-pair f32x2: both operands contiguous pairs) ----
    {
        u64 acc[8][8];
#pragma unroll
        for (int i = 0; i < 8; i++)
#pragma unroll
            for (int j = 0; j < 8; j++) acc[i][j] = 0ull;
#pragma unroll 2
        for (int h = 0; h < HH; h += 2) {
            u64 av[8], bv[8];
#pragma unroll
            for (int i = 0; i < 8; i++) av[i] = *(const u64*)(SA + (8*ty + i)*SSTR + h);
#pragma unroll
            for (int j = 0; j < 8; j++) bv[j] = *(const u64*)(SB + (tx + 16*j)*SSTR + h);
#pragma unroll
            for (int i = 0; i < 8; i++)
#pragma unroll
                for (int j = 0; j < 8; j++) FMA2(acc[i][j], av[i], bv[j]);
        }
        const float scale = 0.08838834764831845f;
#pragma unroll
        for (int i = 0; i < 8; i++)
#pragma unroll
            for (int j = 0; j < 8; j++) {
                float lo, hi; up2(acc[i][j], lo, hi);
                int r = 8*ty + i, c = tx + 16*j;
                SS[r*SSTR + c] = fmaf(lo + hi, scale, SS[r*SSTR + c]);
            }
    }
    __syncthreads();

    // ---- softmax: 2 threads per row ----
    {
        int row = tid >> 1, half = tid & 1;
        float* rp = SS + row*SSTR + 64*half;
        float m = -1e30f;
#pragma unroll
        for (int j = 0; j < 16; j++) {
            float4 v = *(const float4*)(rp + 4*j);
            m = fmaxf(m, fmaxf(fmaxf(v.x, v.y), fmaxf(v.z, v.w)));
        }
        m = fmaxf(m, __shfl_xor_sync(0xffffffffu, m, 1));
        float s = 0.f;
#pragma unroll
        for (int j = 0; j < 16; j++) {
            float4 v = *(float4*)(rp + 4*j);
            v.x = __expf(v.x - m); v.y = __expf(v.y - m);
            v.z = __expf(v.z - m); v.w = __expf(v.w - m);
            s += v.x + v.y + v.z + v.w;
            *(float4*)(rp + 4*j) = v;
        }
        s += __shfl_xor_sync(0xffffffffu, s, 1);
        float inv = 1.f / s;
#pragma unroll
        for (int j = 0; j < 16; j++) {
            float4 v = *(float4*)(rp + 4*j);
            v.x *= inv; v.y *= inv; v.z *= inv; v.w *= inv;
            *(float4*)(rp + 4*j) = v;
        }
    }
    __syncthreads();

    // ================== magnitude path ==================
    for (int i = tid; i < 4096; i += 256) {
        int r = i >> 5, c = (i & 31) * 4;
        *(float4*)(SB + r*SSTR + c) = *(const float4*)(g_vm  + base + (size_t)r*HH + c);
        *(float4*)(SA + r*SSTR + c) = *(const float4*)(g_mag + base + (size_t)r*HH + c);
    }
    __syncthreads();
    {
        u64 acc[8][4];
#pragma unroll
        for (int i = 0; i < 8; i++)
#pragma unroll
            for (int j = 0; j < 4; j++) acc[i][j] = 0ull;
#pragma unroll 2
        for (int jx = 0; jx < NN; jx++) {
            u64 ad[8];
#pragma unroll
            for (int i = 0; i < 8; i++) {
                float a = SS[(8*ty + i)*SSTR + jx];
                ad[i] = pk2(a, a);
            }
            ulonglong2 bv0 = *(const ulonglong2*)(SB + jx*SSTR + 8*tx);
            ulonglong2 bv1 = *(const ulonglong2*)(SB + jx*SSTR + 8*tx + 4);
            u64 bp_[4] = {bv0.x, bv0.y, bv1.x, bv1.y};
#pragma unroll
            for (int i = 0; i < 8; i++)
#pragma unroll
                for (int j = 0; j < 4; j++) FMA2(acc[i][j], ad[i], bp_[j]);
        }
#pragma unroll
        for (int i = 0; i < 8; i++) {
            int r = 8*ty + i;
            float o[8];
#pragma unroll
            for (int j = 0; j < 4; j++) up2(acc[i][j], o[2*j], o[2*j+1]);
            float4 r0 = *(const float4*)(SA + r*SSTR + 8*tx);
            float4 r1 = *(const float4*)(SA + r*SSTR + 8*tx + 4);
            r0.x += o[0]; r0.y += o[1]; r0.z += o[2]; r0.w += o[3];
            r1.x += o[4]; r1.y += o[5]; r1.z += o[6]; r1.w += o[7];
            *(float4*)(SA + r*SSTR + 8*tx)     = r0;
            *(float4*)(SA + r*SSTR + 8*tx + 4) = r1;
        }
    }
    __syncthreads();

    // ---- LayerNorm: 2 threads per row ----
    {
        int row = tid >> 1, half = tid & 1;
        float* rp = SA + row*SSTR + 64*half;
        float su = 0.f;
#pragma unroll
        for (int j = 0; j < 16; j++) {
            float4 v = *(const float4*)(rp + 4*j);
            su += v.x + v.y + v.z + v.w;
        }
        su += __shfl_xor_sync(0xffffffffu, su, 1);
        float mu = su * (1.f/128.f);
        float var = 0.f;
#pragma unroll
        for (int j = 0; j < 16; j++) {
            float4 v = *(const float4*)(rp + 4*j);
            float d0 = v.x - mu, d1 = v.y - mu, d2 = v.z - mu, d3 = v.w - mu;
            var = fmaf(d0, d0, var); var = fmaf(d1, d1, var);
            var = fmaf(d2, d2, var); var = fmaf(d3, d3, var);
        }
        var += __shfl_xor_sync(0xffffffffu, var, 1);
        float rs = rsqrtf(var * (1.f/128.f) + 1e-5f);
        const float* gp = lng + l*HH + 64*half;
        const float* bp2 = lnb + l*HH + 64*half;
#pragma unroll
        for (int j = 0; j < 16; j++) {
            float4 v = *(float4*)(rp + 4*j);
            float4 g = *(const float4*)(gp + 4*j);
            float4 be2 = *(const float4*)(bp2 + 4*j);
            v.x = fmaf(g.x, (v.x - mu)*rs, be2.x);
            v.y = fmaf(g.y, (v.y - mu)*rs, be2.y);
            v.z = fmaf(g.z, (v.z - mu)*rs, be2.z);
            v.w = fmaf(g.w, (v.w - mu)*rs, be2.w);
            *(float4*)(rp + 4*j) = v;
        }
    }
    __syncthreads();
    for (int i = tid; i < 4096; i += 256) {
        int r = i >> 5, c = (i & 31) * 4;
        *(float4*)(g_mag + base + (size_t)r*HH + c) = *(const float4*)(SA + r*SSTR + c);
    }
    __syncthreads();

    // ================== phase path ==================
    for (int i = tid; i < 4096; i += 256) {
        int r = i >> 5, c = (i & 31) * 4;
        *(float4*)(SB + r*SSTR + c) = *(const float4*)(g_vp + base + (size_t)r*HH + c);
        *(float4*)(SA + r*SSTR + c) = *(const float4*)(g_ph + base + (size_t)r*HH + c);
    }
    __syncthreads();
    {
        u64 acc[8][4];
#pragma unroll
        for (int i = 0; i < 8; i++)
#pragma unroll
            for (int j = 0; j < 4; j++) acc[i][j] = 0ull;
#pragma unroll 2
        for (int jx = 0; jx < NN; jx++) {
            u64 ad[8];
#pragma unroll
            for (int i = 0; i < 8; i++) {
                float a = SS[(8*ty + i)*SSTR + jx];
                ad[i] = pk2(a, a);
            }
            ulonglong2 bv0 = *(const ulonglong2*)(SB + jx*SSTR + 8*tx);
            ulonglong2 bv1 = *(const ulonglong2*)(SB + jx*SSTR + 8*tx + 4);
            u64 bp_[4] = {bv0.x, bv0.y, bv1.x, bv1.y};
#pragma unroll
            for (int i = 0; i < 8; i++)
#pragma unroll
                for (int j = 0; j < 4; j++) FMA2(acc[i][j], ad[i], bp_[j]);
        }
#pragma unroll
        for (int i = 0; i < 8; i++) {
            int r = 8*ty + i;
            float o[8];
#pragma unroll
            for (int j = 0; j < 4; j++) up2(acc[i][j], o[2*j], o[2*j+1]);
            float4 r0 = *(const float4*)(SA + r*SSTR + 8*tx);
            float4 r1 = *(const float4*)(SA + r*SSTR + 8*tx + 4);
            r0.x += o[0]; r0.y += o[1]; r0.z += o[2]; r0.w += o[3];
            r1.x += o[4]; r1.y += o[5]; r1.z += o[6]; r1.w += o[7];
            *(float4*)(SA + r*SSTR + 8*tx)     = r0;
            *(float4*)(SA + r*SSTR + 8*tx + 4) = r1;
        }
    }
    __syncthreads();
    for (int i = tid; i < 4096; i += 256) {
        int r = i >> 5, c = (i & 31) * 4;
        *(float4*)(g_ph + base + (size_t)r*HH + c) = *(const float4*)(SA + r*SSTR + c);
    }
}

// ---------------- K3: real projection + pooling + MLP head ----------------
__global__ void k_head(const float* __restrict__ rpW, const float* __restrict__ rpb,
                       const float* __restrict__ h1W, const float* __restrict__ h1b,
                       const float* __restrict__ h2W, const float* __restrict__ h2b,
                       float* __restrict__ out)
{
    int b = blockIdx.x, t = threadIdx.x;
    __shared__ float sS[2*HH];
    __shared__ float sp[2*HH];
    __shared__ float sr[HH];
    size_t base = (size_t)b*NH;

    float ac = 0.f, as = 0.f;
    for (int n = 0; n < NN; n++) {
        float m = g_mag[base + (size_t)n*HH + t];
        float p = g_ph [base + (size_t)n*HH + t];
        float si, co;
        sincosf(p, &si, &co);
        ac = fmaf(m, co, ac);
        as = fmaf(m, si, as);
    }
    sS[t] = ac; sS[HH + t] = as;
    __syncthreads();

    float d = 0.f;
    for (int c = 0; c < 2*HH; c++) d = fmaf(sS[c], rpW[(size_t)c*HH + t], d);
    float sumr = d + 128.f * rpb[t];
    sp[t]      = sumr * (1.f/128.f);
    sp[HH + t] = sumr;
    __syncthreads();

    float hv = h1b[t];
    for (int c = 0; c < 2*HH; c++) hv = fmaf(sp[c], h1W[(size_t)c*HH + t], hv);
    hv = hv / (1.f + expf(-hv));
    sr[t] = hv * h2W[t];
    __syncthreads();

    for (int s = 64; s >= 1; s >>= 1) {
        if (t < s) sr[t] += sr[t + s];
        __syncthreads();
    }
    if (t == 0) out[b] = sr[0] + h2b[0];
}

// ---------------- launch ----------------
extern "C" void kernel_launch(void* const* d_in, const int* in_sizes, int n_in,
                              void* d_out, int out_size)
{
    const float* at   = (const float*)d_in[0];
    const float* sph  = (const float*)d_in[1];
    const int*   ei   = (const int*)  d_in[2];
    const float* ea   = (const float*)d_in[3];
    const float* Wm   = (const float*)d_in[4];
    const float* bm   = (const float*)d_in[5];
    const float* Wp   = (const float*)d_in[6];
    const float* bp   = (const float*)d_in[7];
    const float* Wq   = (const float*)d_in[8];
    const float* bq   = (const float*)d_in[9];
    const float* Wk   = (const float*)d_in[10];
    const float* bk   = (const float*)d_in[11];
    const float* Wvm  = (const float*)d_in[12];
    const float* bvm  = (const float*)d_in[13];
    const float* Wvp  = (const float*)d_in[14];
    const float* bvp  = (const float*)d_in[15];
    const float* We   = (const float*)d_in[16];
    const float* be   = (const float*)d_in[17];
    const float* ds   = (const float*)d_in[18];
    const float* lng  = (const float*)d_in[19];
    const float* lnb  = (const float*)d_in[20];
    const float* rpW  = (const float*)d_in[21];
    const float* rpb  = (const float*)d_in[22];
    const float* h1W  = (const float*)d_in[23];
    const float* h1b  = (const float*)d_in[24];
    const float* h2W  = (const float*)d_in[25];
    const float* h2b  = (const float*)d_in[26];
    float* out = (float*)d_out;

    void *p_mag, *p_ph, *p_q, *p_k, *p_vm, *p_vp;
    cudaGetSymbolAddress(&p_mag, g_mag);
    cudaGetSymbolAddress(&p_ph,  g_ph);
    cudaGetSymbolAddress(&p_q,   g_q);
    cudaGetSymbolAddress(&p_k,   g_k);
    cudaGetSymbolAddress(&p_vm,  g_vm);
    cudaGetSymbolAddress(&p_vp,  g_vp);

    size_t attn_smem = (size_t)3 * NN * SSTR * sizeof(float);  // 202752 B
    cudaFuncSetAttribute(k_attn, cudaFuncAttributeMaxDynamicSharedMemorySize, (int)attn_smem);

    k_embed<<<BB, 128>>>(at, sph, Wm, bm, Wp, bp);

    for (int l = 0; l < LL; l++) {
        dim3 pg(1024, 4);
        k_proj<<<pg, 256>>>((const float*)p_mag, (const float*)p_ph,
                            Wq, bq, Wk, bk, Wvm, bvm, Wvp, bvp,
                            (float*)p_q, (float*)p_k, (float*)p_vm, (float*)p_vp, l);
        k_attn<<<BB, 256, attn_smem>>>(ei, ea, We, be, ds, lng, lnb, l);
    }

    k_head<<<BB, 128>>>(rpW, rpb, h1W, h1b, h2W, h2b, out);
}

// round 6
// speedup vs baseline: 1.4024x; 1.1105x over previous
#include <cuda_runtime.h>
#include <math.h>
#include <stdint.h>

#define BB   1024
#define NN   128
#define EE   1024
#define HH   128
#define LL   4
#define INDIM 16
#define DIN  19
#define EDIM 4
#define NH   (NN*HH)      // 16384
#define HSQ  (HH*HH)      // 16384

#define ASTR 132          // stride (words) for A-pattern smem buffers
#define BSTR 136          // stride (words) for B-pattern smem buffers

// ---------------- device scratch ----------------
__device__ float g_mag[(size_t)BB*NH];
__device__ float g_ph [(size_t)BB*NH];
__device__ float g_q  [(size_t)BB*NH];
__device__ float g_k  [(size_t)BB*NH];
__device__ float g_vm [(size_t)BB*NH];
__device__ float g_vp [(size_t)BB*NH];

// ---------------- helpers ----------------
__device__ __forceinline__ float tf32f(float x) {
    float r; asm("cvt.rna.tf32.f32 %0, %1;" : "=f"(r) : "f"(x)); return r;
}
// split x into hi + lo tf32 parts (3xTF32 trick)
__device__ __forceinline__ void split3(float x, uint32_t& hi, uint32_t& lo) {
    float h = tf32f(x);
    hi = __float_as_uint(h);
    lo = __float_as_uint(tf32f(x - h));
}
__device__ __forceinline__ void mma8(float* c, const uint32_t* a, uint32_t b0, uint32_t b1) {
    asm volatile("mma.sync.aligned.m16n8k8.row.col.f32.tf32.tf32.f32 "
        "{%0,%1,%2,%3}, {%4,%5,%6,%7}, {%8,%9}, {%0,%1,%2,%3};"
        : "+f"(c[0]), "+f"(c[1]), "+f"(c[2]), "+f"(c[3])
        : "r"(a[0]), "r"(a[1]), "r"(a[2]), "r"(a[3]), "r"(b0), "r"(b1));
}
// full 3xTF32 update for one (mt-pair, nt): 6 mma
__device__ __forceinline__ void mma3x(float* c0, float* c1,
                                      const uint32_t* ah0, const uint32_t* al0,
                                      const uint32_t* ah1, const uint32_t* al1,
                                      uint32_t bh0, uint32_t bh1, uint32_t bl0, uint32_t bl1) {
    mma8(c0, ah0, bh0, bh1);
    mma8(c1, ah1, bh0, bh1);
    mma8(c0, ah0, bl0, bl1);
    mma8(c1, ah1, bl0, bl1);
    mma8(c0, al0, bh0, bh1);
    mma8(c1, al1, bh0, bh1);
}

// ---------------- K0: complex embedding ----------------
__global__ void k_embed(const float* __restrict__ at, const float* __restrict__ sph,
                        const float* __restrict__ Wm, const float* __restrict__ bm,
                        const float* __restrict__ Wp, const float* __restrict__ bp)
{
    int b = blockIdx.x, t = threadIdx.x;
    __shared__ float sx[NN][20];
    for (int i = t; i < NN*DIN; i += blockDim.x) {
        int n = i / DIN, d = i % DIN;
        sx[n][d] = (d < INDIM) ? at[((size_t)b*NN + n)*INDIM + d]
                               : sph[((size_t)b*NN + n)*3 + (d - INDIM)];
    }
    __syncthreads();
    float wm[DIN], wp[DIN];
#pragma unroll
    for (int d = 0; d < DIN; d++) { wm[d] = Wm[d*HH + t]; wp[d] = Wp[d*HH + t]; }
    float bmv = bm[t], bpv = bp[t];
    size_t base = (size_t)b*NH;
    for (int n = 0; n < NN; n++) {
        float am = bmv, ap = bpv;
#pragma unroll
        for (int d = 0; d < DIN; d++) { float x = sx[n][d]; am = fmaf(x, wm[d], am); ap = fmaf(x, wp[d], ap); }
        g_mag[base + (size_t)n*HH + t] = am;
        g_ph [base + (size_t)n*HH + t] = ap;
    }
}

// ---------------- K1: projection GEMM via 3xTF32 mma.sync ----------------
// grid = (1024, 4): y picks {q,k,vm,vp}. CTA computes 128x128, K=128. 256 thr.
__global__ __launch_bounds__(256) void k_proj_mma(
    const float* __restrict__ Am, const float* __restrict__ Ap,
    const float* __restrict__ Wq, const float* __restrict__ bq,
    const float* __restrict__ Wk, const float* __restrict__ bk,
    const float* __restrict__ Wvm, const float* __restrict__ bvm,
    const float* __restrict__ Wvp, const float* __restrict__ bvp,
    float* __restrict__ Cq, float* __restrict__ Ck,
    float* __restrict__ Cvm, float* __restrict__ Cvp, int l)
{
    extern __shared__ float smf[];
    float* SAf = smf;                 // [128][ASTR] fp32 A
    float* SWf = smf + NN*ASTR;       // [128][BSTR] fp32 W

    int p = blockIdx.y;
    const float* A; const float* W; const float* bias; float* C;
    if      (p == 0) { A = Am; W = Wq  + (size_t)l*HSQ; bias = bq  + l*HH; C = Cq;  }
    else if (p == 1) { A = Am; W = Wk  + (size_t)l*HSQ; bias = bk  + l*HH; C = Ck;  }
    else if (p == 2) { A = Am; W = Wvm + (size_t)l*HSQ; bias = bvm + l*HH; C = Cvm; }
    else             { A = Ap; W = Wvp + (size_t)l*HSQ; bias = bvp + l*HH; C = Cvp; }

    int tid = threadIdx.x;
    int wid = tid >> 5, lane = tid & 31;
    int gid = lane >> 2, tig = lane & 3;
    int wm = (wid & 3) * 32, wn = (wid >> 2) * 64;
    size_t m0 = (size_t)blockIdx.x * 128;

    const float4* Ag = (const float4*)(A + m0*HH);
    const float4* Wg = (const float4*)W;
#pragma unroll
    for (int it = 0; it < 16; it++) {
        int idx = tid + 256*it;
        int r = idx >> 5, c = (idx & 31) * 4;
        *(float4*)(SAf + r*ASTR + c) = Ag[idx];
        *(float4*)(SWf + r*BSTR + c) = Wg[idx];
    }
    __syncthreads();

    float acc[2][8][4];
#pragma unroll
    for (int i = 0; i < 2; i++)
#pragma unroll
        for (int j = 0; j < 8; j++)
#pragma unroll
            for (int q = 0; q < 4; q++) acc[i][j][q] = 0.f;

#pragma unroll
    for (int k0 = 0; k0 < HH; k0 += 8) {
        uint32_t ah[2][4], al[2][4];
#pragma unroll
        for (int mt = 0; mt < 2; mt++) {
            int rb = wm + mt*16;
            split3(SAf[(rb + gid    )*ASTR + k0 + tig    ], ah[mt][0], al[mt][0]);
            split3(SAf[(rb + gid + 8)*ASTR + k0 + tig    ], ah[mt][1], al[mt][1]);
            split3(SAf[(rb + gid    )*ASTR + k0 + tig + 4], ah[mt][2], al[mt][2]);
            split3(SAf[(rb + gid + 8)*ASTR + k0 + tig + 4], ah[mt][3], al[mt][3]);
        }
#pragma unroll
        for (int nt = 0; nt < 8; nt++) {
            int nb = wn + nt*8;
            uint32_t bh0, bl0, bh1, bl1;
            split3(SWf[(k0 + tig    )*BSTR + nb + gid], bh0, bl0);
            split3(SWf[(k0 + tig + 4)*BSTR + nb + gid], bh1, bl1);
            mma3x(acc[0][nt], acc[1][nt], ah[0], al[0], ah[1], al[1], bh0, bh1, bl0, bl1);
        }
    }

#pragma unroll
    for (int mt = 0; mt < 2; mt++) {
        int r0 = (int)m0 + wm + mt*16 + gid;
#pragma unroll
        for (int nt = 0; nt < 8; nt++) {
            int c = wn + nt*8 + 2*tig;
            float b0 = __ldg(bias + c), b1 = __ldg(bias + c + 1);
            *(float2*)(C + (size_t)r0*HH + c)       = make_float2(acc[mt][nt][0] + b0, acc[mt][nt][1] + b1);
            *(float2*)(C + (size_t)(r0+8)*HH + c)   = make_float2(acc[mt][nt][2] + b0, acc[mt][nt][3] + b1);
        }
    }
}

// ---------------- K2: per-molecule attention layer (3xTF32 mma.sync) ----------------
__global__ __launch_bounds__(256) void k_attn(
    const int* __restrict__ ei, const float* __restrict__ ea,
    const float* __restrict__ We, const float* __restrict__ be,
    const float* __restrict__ ds,
    const float* __restrict__ lng, const float* __restrict__ lnb,
    int l)
{
    extern __shared__ float sm[];
    float* SA = sm;                              // [128][ASTR] Q / residual
    float* SB = sm + NN*ASTR;                    // [128][BSTR] K (stride ASTR) / V (stride BSTR)
    float* SS = sm + NN*ASTR + NN*BSTR;          // [128][ASTR] scores / probs

    int b = blockIdx.x, tid = threadIdx.x;
    int wid = tid >> 5, lane = tid & 31;
    int gid = lane >> 2, tig = lane & 3;
    int wm = (wid & 3) * 32, wn = (wid >> 2) * 64;
    size_t base = (size_t)b*NH;

    // ---- load Q (stride ASTR) and K (stride ASTR, row-major = B^T pattern); zero SS ----
#pragma unroll
    for (int it = 0; it < 16; it++) {
        int idx = tid + 256*it;
        int r = idx >> 5, c = (idx & 31) * 4;
        *(float4*)(SA + r*ASTR + c) = *(const float4*)(g_q + base + (size_t)r*HH + c);
        *(float4*)(SB + r*ASTR + c) = *(const float4*)(g_k + base + (size_t)r*HH + c);
    }
    for (int i = tid; i < NN*ASTR/4; i += 256) ((float4*)SS)[i] = make_float4(0.f, 0.f, 0.f, 0.f);
    __syncthreads();

    // ---- edge bias scatter into SS ----
    {
        float w0 = We[l*4+0], w1 = We[l*4+1], w2 = We[l*4+2], w3 = We[l*4+3];
        float beL = be[l], dsL = ds[l];
        for (int e = tid; e < EE; e += 256) {
            int i0 = ei[(size_t)b*2*EE + e];
            int j0 = ei[(size_t)b*2*EE + EE + e];
            const float* a = ea + ((size_t)b*EE + e)*EDIM;
            float v = fmaf(a[0], w0, fmaf(a[1], w1, fmaf(a[2], w2, fmaf(a[3], w3, beL)))) + dsL*a[0];
            atomicAdd(&SS[i0*ASTR + j0], v);
        }
    }
    __syncthreads();

    // ---- scores = Q @ K^T * scale + bias ----
    {
        float acc[2][8][4];
#pragma unroll
        for (int i = 0; i < 2; i++)
#pragma unroll
            for (int j = 0; j < 8; j++)
#pragma unroll
                for (int q = 0; q < 4; q++) acc[i][j][q] = 0.f;
#pragma unroll
        for (int k0 = 0; k0 < HH; k0 += 8) {
            uint32_t ah[2][4], al[2][4];
#pragma unroll
            for (int mt = 0; mt < 2; mt++) {
                int rb = wm + mt*16;
                split3(SA[(rb + gid    )*ASTR + k0 + tig    ], ah[mt][0], al[mt][0]);
                split3(SA[(rb + gid + 8)*ASTR + k0 + tig    ], ah[mt][1], al[mt][1]);
                split3(SA[(rb + gid    )*ASTR + k0 + tig + 4], ah[mt][2], al[mt][2]);
                split3(SA[(rb + gid + 8)*ASTR + k0 + tig + 4], ah[mt][3], al[mt][3]);
            }
#pragma unroll
            for (int nt = 0; nt < 8; nt++) {
                int nb = wn + nt*8;
                uint32_t bh0, bl0, bh1, bl1;
                split3(SB[(nb + gid)*ASTR + k0 + tig    ], bh0, bl0);
                split3(SB[(nb + gid)*ASTR + k0 + tig + 4], bh1, bl1);
                mma3x(acc[0][nt], acc[1][nt], ah[0], al[0], ah[1], al[1], bh0, bh1, bl0, bl1);
            }
        }
        const float scale = 0.08838834764831845f;
#pragma unroll
        for (int mt = 0; mt < 2; mt++) {
            int r0 = wm + mt*16 + gid;
#pragma unroll
            for (int nt = 0; nt < 8; nt++) {
                int c = wn + nt*8 + 2*tig;
                SS[r0*ASTR + c]       = fmaf(acc[mt][nt][0], scale, SS[r0*ASTR + c]);
                SS[r0*ASTR + c + 1]   = fmaf(acc[mt][nt][1], scale, SS[r0*ASTR + c + 1]);
                SS[(r0+8)*ASTR + c]   = fmaf(acc[mt][nt][2], scale, SS[(r0+8)*ASTR + c]);
                SS[(r0+8)*ASTR + c+1] = fmaf(acc[mt][nt][3], scale, SS[(r0+8)*ASTR + c + 1]);
            }
        }
    }
    __syncthreads();

    // ---- softmax: 2 threads per row, full fp32 output ----
    {
        int row = tid >> 1, half = tid & 1;
        float* rp = SS + row*ASTR + 64*half;
        float m = -1e30f;
#pragma unroll
        for (int j = 0; j < 16; j++) {
            float4 v = *(const float4*)(rp + 4*j);
            m = fmaxf(m, fmaxf(fmaxf(v.x, v.y), fmaxf(v.z, v.w)));
        }
        m = fmaxf(m, __shfl_xor_sync(0xffffffffu, m, 1));
        float s = 0.f;
#pragma unroll
        for (int j = 0; j < 16; j++) {
            float4 v = *(float4*)(rp + 4*j);
            v.x = __expf(v.x - m); v.y = __expf(v.y - m);
            v.z = __expf(v.z - m); v.w = __expf(v.w - m);
            s += v.x + v.y + v.z + v.w;
            *(float4*)(rp + 4*j) = v;
        }
        s += __shfl_xor_sync(0xffffffffu, s, 1);
        float inv = 1.f / s;
#pragma unroll
        for (int j = 0; j < 16; j++) {
            float4 v = *(float4*)(rp + 4*j);
            v.x *= inv; v.y *= inv; v.z *= inv; v.w *= inv;
            *(float4*)(rp + 4*j) = v;
        }
    }
    __syncthreads();

    // ================== two AV passes: vm (with LN) then vp ==================
#pragma unroll 1
    for (int pass = 0; pass < 2; pass++) {
        const float* Vsrc = pass == 0 ? g_vm : g_vp;
        const float* Rsrc = pass == 0 ? g_mag : g_ph;
        float*       Rdst = pass == 0 ? g_mag : g_ph;

#pragma unroll
        for (int it = 0; it < 16; it++) {
            int idx = tid + 256*it;
            int r = idx >> 5, c = (idx & 31) * 4;
            *(float4*)(SB + r*BSTR + c) = *(const float4*)(Vsrc + base + (size_t)r*HH + c);
            *(float4*)(SA + r*ASTR + c) = *(const float4*)(Rsrc + base + (size_t)r*HH + c);
        }
        __syncthreads();

        {
            float acc[2][8][4];
#pragma unroll
            for (int i = 0; i < 2; i++)
#pragma unroll
                for (int j = 0; j < 8; j++)
#pragma unroll
                    for (int q = 0; q < 4; q++) acc[i][j][q] = 0.f;
#pragma unroll
            for (int k0 = 0; k0 < NN; k0 += 8) {
                uint32_t ah[2][4], al[2][4];
#pragma unroll
                for (int mt = 0; mt < 2; mt++) {
                    int rb = wm + mt*16;
                    split3(SS[(rb + gid    )*ASTR + k0 + tig    ], ah[mt][0], al[mt][0]);
                    split3(SS[(rb + gid + 8)*ASTR + k0 + tig    ], ah[mt][1], al[mt][1]);
                    split3(SS[(rb + gid    )*ASTR + k0 + tig + 4], ah[mt][2], al[mt][2]);
                    split3(SS[(rb + gid + 8)*ASTR + k0 + tig + 4], ah[mt][3], al[mt][3]);
                }
#pragma unroll
                for (int nt = 0; nt < 8; nt++) {
                    int nb = wn + nt*8;
                    uint32_t bh0, bl0, bh1, bl1;
                    split3(SB[(k0 + tig    )*BSTR + nb + gid], bh0, bl0);
                    split3(SB[(k0 + tig + 4)*BSTR + nb + gid], bh1, bl1);
                    mma3x(acc[0][nt], acc[1][nt], ah[0], al[0], ah[1], al[1], bh0, bh1, bl0, bl1);
                }
            }
#pragma unroll
            for (int mt = 0; mt < 2; mt++) {
                int r0 = wm + mt*16 + gid;
#pragma unroll
                for (int nt = 0; nt < 8; nt++) {
                    int c = wn + nt*8 + 2*tig;
                    float2 v0 = *(float2*)(SA + r0*ASTR + c);
                    float2 v1 = *(float2*)(SA + (r0+8)*ASTR + c);
                    v0.x += acc[mt][nt][0]; v0.y += acc[mt][nt][1];
                    v1.x += acc[mt][nt][2]; v1.y += acc[mt][nt][3];
                    *(float2*)(SA + r0*ASTR + c)     = v0;
                    *(float2*)(SA + (r0+8)*ASTR + c) = v1;
                }
            }
        }
        __syncthreads();

        if (pass == 0) {
            // LayerNorm rows of SA (magnitude only)
            int row = tid >> 1, half = tid & 1;
            float* rp = SA + row*ASTR + 64*half;
            float su = 0.f;
#pragma unroll
            for (int j = 0; j < 16; j++) {
                float4 v = *(const float4*)(rp + 4*j);
                su += v.x + v.y + v.z + v.w;
            }
            su += __shfl_xor_sync(0xffffffffu, su, 1);
            float mu = su * (1.f/128.f);
            float var = 0.f;
#pragma unroll
            for (int j = 0; j < 16; j++) {
                float4 v = *(const float4*)(rp + 4*j);
                float d0 = v.x - mu, d1 = v.y - mu, d2 = v.z - mu, d3 = v.w - mu;
                var = fmaf(d0, d0, var); var = fmaf(d1, d1, var);
                var = fmaf(d2, d2, var); var = fmaf(d3, d3, var);
            }
            var += __shfl_xor_sync(0xffffffffu, var, 1);
            float rs = rsqrtf(var * (1.f/128.f) + 1e-5f);
            const float* gp  = lng + l*HH + 64*half;
            const float* bp2 = lnb + l*HH + 64*half;
#pragma unroll
            for (int j = 0; j < 16; j++) {
                float4 v = *(float4*)(rp + 4*j);
                float4 g = *(const float4*)(gp + 4*j);
                float4 be2 = *(const float4*)(bp2 + 4*j);
                v.x = fmaf(g.x, (v.x - mu)*rs, be2.x);
                v.y = fmaf(g.y, (v.y - mu)*rs, be2.y);
                v.z = fmaf(g.z, (v.z - mu)*rs, be2.z);
                v.w = fmaf(g.w, (v.w - mu)*rs, be2.w);
                *(float4*)(rp + 4*j) = v;
            }
            __syncthreads();
        }

#pragma unroll
        for (int it = 0; it < 16; it++) {
            int idx = tid + 256*it;
            int r = idx >> 5, c = (idx & 31) * 4;
            *(float4*)(Rdst + base + (size_t)r*HH + c) = *(const float4*)(SA + r*ASTR + c);
        }
        __syncthreads();
    }
}

// ---------------- K3: head ----------------
__global__ void k_head(const float* __restrict__ rpW, const float* __restrict__ rpb,
                       const float* __restrict__ h1W, const float* __restrict__ h1b,
                       const float* __restrict__ h2W, const float* __restrict__ h2b,
                       float* __restrict__ out)
{
    int b = blockIdx.x, t = threadIdx.x;
    __shared__ float sS[2*HH];
    __shared__ float sp[2*HH];
    __shared__ float sr[HH];
    size_t base = (size_t)b*NH;

    float ac = 0.f, as = 0.f;
    for (int n = 0; n < NN; n++) {
        float m = g_mag[base + (size_t)n*HH + t];
        float p = g_ph [base + (size_t)n*HH + t];
        float si, co;
        sincosf(p, &si, &co);
        ac = fmaf(m, co, ac);
        as = fmaf(m, si, as);
    }
    sS[t] = ac; sS[HH + t] = as;
    __syncthreads();

    float d = 0.f;
    for (int c = 0; c < 2*HH; c++) d = fmaf(sS[c], rpW[(size_t)c*HH + t], d);
    float sumr = d + 128.f * rpb[t];
    sp[t]      = sumr * (1.f/128.f);
    sp[HH + t] = sumr;
    __syncthreads();

    float hv = h1b[t];
    for (int c = 0; c < 2*HH; c++) hv = fmaf(sp[c], h1W[(size_t)c*HH + t], hv);
    hv = hv / (1.f + expf(-hv));
    sr[t] = hv * h2W[t];
    __syncthreads();

    for (int s = 64; s >= 1; s >>= 1) {
        if (t < s) sr[t] += sr[t + s];
        __syncthreads();
    }
    if (t == 0) out[b] = sr[0] + h2b[0];
}

// ---------------- launch ----------------
extern "C" void kernel_launch(void* const* d_in, const int* in_sizes, int n_in,
                              void* d_out, int out_size)
{
    const float* at   = (const float*)d_in[0];
    const float* sph  = (const float*)d_in[1];
    const int*   ei   = (const int*)  d_in[2];
    const float* ea   = (const float*)d_in[3];
    const float* Wm   = (const float*)d_in[4];
    const float* bm   = (const float*)d_in[5];
    const float* Wp   = (const float*)d_in[6];
    const float* bp   = (const float*)d_in[7];
    const float* Wq   = (const float*)d_in[8];
    const float* bq   = (const float*)d_in[9];
    const float* Wk   = (const float*)d_in[10];
    const float* bk   = (const float*)d_in[11];
    const float* Wvm  = (const float*)d_in[12];
    const float* bvm  = (const float*)d_in[13];
    const float* Wvp  = (const float*)d_in[14];
    const float* bvp  = (const float*)d_in[15];
    const float* We   = (const float*)d_in[16];
    const float* be   = (const float*)d_in[17];
    const float* ds   = (const float*)d_in[18];
    const float* lng  = (const float*)d_in[19];
    const float* lnb  = (const float*)d_in[20];
    const float* rpW  = (const float*)d_in[21];
    const float* rpb  = (const float*)d_in[22];
    const float* h1W  = (const float*)d_in[23];
    const float* h1b  = (const float*)d_in[24];
    const float* h2W  = (const float*)d_in[25];
    const float* h2b  = (const float*)d_in[26];
    float* out = (float*)d_out;

    void *p_mag, *p_ph, *p_q, *p_k, *p_vm, *p_vp;
    cudaGetSymbolAddress(&p_mag, g_mag);
    cudaGetSymbolAddress(&p_ph,  g_ph);
    cudaGetSymbolAddress(&p_q,   g_q);
    cudaGetSymbolAddress(&p_k,   g_k);
    cudaGetSymbolAddress(&p_vm,  g_vm);
    cudaGetSymbolAddress(&p_vp,  g_vp);

    size_t proj_smem = (size_t)(NN*ASTR + NN*BSTR) * 4;              // 137216
    size_t attn_smem = (size_t)(NN*ASTR + NN*BSTR + NN*ASTR) * 4;    // 204800
    cudaFuncSetAttribute(k_proj_mma, cudaFuncAttributeMaxDynamicSharedMemorySize, (int)proj_smem);
    cudaFuncSetAttribute(k_attn,     cudaFuncAttributeMaxDynamicSharedMemorySize, (int)attn_smem);

    k_embed<<<BB, 128>>>(at, sph, Wm, bm, Wp, bp);

    for (int l = 0; l < LL; l++) {
        dim3 pg(1024, 4);
        k_proj_mma<<<pg, 256, proj_smem>>>((const float*)p_mag, (const float*)p_ph,
                                           Wq, bq, Wk, bk, Wvm, bvm, Wvp, bvp,
                                           (float*)p_q, (float*)p_k, (float*)p_vm, (float*)p_vp, l);
        k_attn<<<BB, 256, attn_smem>>>(ei, ea, We, be, ds, lng, lnb, l);
    }

    k_head<<<BB, 128>>>(rpW, rpb, h1W, h1b, h2W, h2b, out);
}

// round 7
// speedup vs baseline: 1.5956x; 1.1378x over previous
#include <cuda_runtime.h>
#include <math.h>
#include <stdint.h>

#define BB   1024
#define NN   128
#define EE   1024
#define HH   128
#define LL   4
#define INDIM 16
#define DIN  19
#define EDIM 4
#define NH   (NN*HH)      // 16384
#define HSQ  (HH*HH)      // 16384

#define ASTR 132          // stride (words) for A-pattern smem buffers
#define BSTR 136          // stride (words) for B-pattern smem buffers

// ---------------- device scratch ----------------
__device__ float g_mag[(size_t)BB*NH];
__device__ float g_ph [(size_t)BB*NH];
__device__ float g_q  [(size_t)BB*NH];
__device__ float g_k  [(size_t)BB*NH];
__device__ float g_vm [(size_t)BB*NH];
__device__ float g_vp [(size_t)BB*NH];

// ---------------- helpers ----------------
__device__ __forceinline__ float tf32f(float x) {
    float r; asm("cvt.rna.tf32.f32 %0, %1;" : "=f"(r) : "f"(x)); return r;
}
// split x into hi + lo tf32 parts (3xTF32 trick)
__device__ __forceinline__ void split3(float x, uint32_t& hi, uint32_t& lo) {
    float h = tf32f(x);
    hi = __float_as_uint(h);
    lo = __float_as_uint(tf32f(x - h));
}
__device__ __forceinline__ void mma8(float* c, const uint32_t* a, uint32_t b0, uint32_t b1) {
    asm volatile("mma.sync.aligned.m16n8k8.row.col.f32.tf32.tf32.f32 "
        "{%0,%1,%2,%3}, {%4,%5,%6,%7}, {%8,%9}, {%0,%1,%2,%3};"
        : "+f"(c[0]), "+f"(c[1]), "+f"(c[2]), "+f"(c[3])
        : "r"(a[0]), "r"(a[1]), "r"(a[2]), "r"(a[3]), "r"(b0), "r"(b1));
}
// 3xTF32 update for a pair of m-tiles sharing one B fragment: 6 mma
__device__ __forceinline__ void mma3x(float* c0, float* c1,
                                      const uint32_t* ah0, const uint32_t* al0,
                                      const uint32_t* ah1, const uint32_t* al1,
                                      uint32_t bh0, uint32_t bh1, uint32_t bl0, uint32_t bl1) {
    mma8(c0, ah0, bh0, bh1);
    mma8(c1, ah1, bh0, bh1);
    mma8(c0, ah0, bl0, bl1);
    mma8(c1, ah1, bl0, bl1);
    mma8(c0, al0, bh0, bh1);
    mma8(c1, al1, bh0, bh1);
}

// ---------------- K0: complex embedding ----------------
__global__ void k_embed(const float* __restrict__ at, const float* __restrict__ sph,
                        const float* __restrict__ Wm, const float* __restrict__ bm,
                        const float* __restrict__ Wp, const float* __restrict__ bp)
{
    int b = blockIdx.x, t = threadIdx.x;
    __shared__ float sx[NN][20];
    for (int i = t; i < NN*DIN; i += blockDim.x) {
        int n = i / DIN, d = i % DIN;
        sx[n][d] = (d < INDIM) ? at[((size_t)b*NN + n)*INDIM + d]
                               : sph[((size_t)b*NN + n)*3 + (d - INDIM)];
    }
    __syncthreads();
    float wm[DIN], wp[DIN];
#pragma unroll
    for (int d = 0; d < DIN; d++) { wm[d] = Wm[d*HH + t]; wp[d] = Wp[d*HH + t]; }
    float bmv = bm[t], bpv = bp[t];
    size_t base = (size_t)b*NH;
    for (int n = 0; n < NN; n++) {
        float am = bmv, ap = bpv;
#pragma unroll
        for (int d = 0; d < DIN; d++) { float x = sx[n][d]; am = fmaf(x, wm[d], am); ap = fmaf(x, wp[d], ap); }
        g_mag[base + (size_t)n*HH + t] = am;
        g_ph [base + (size_t)n*HH + t] = ap;
    }
}

// ---------------- K1: projection GEMM via 3xTF32 mma.sync (512 thr) ----------------
// grid = (1024, 4): y picks {q,k,vm,vp}. CTA computes 128x128, K=128.
// 16 warps in 4x4 grid: each warp owns a 32x32 output tile.
__global__ __launch_bounds__(512) void k_proj_mma(
    const float* __restrict__ Am, const float* __restrict__ Ap,
    const float* __restrict__ Wq, const float* __restrict__ bq,
    const float* __restrict__ Wk, const float* __restrict__ bk,
    const float* __restrict__ Wvm, const float* __restrict__ bvm,
    const float* __restrict__ Wvp, const float* __restrict__ bvp,
    float* __restrict__ Cq, float* __restrict__ Ck,
    float* __restrict__ Cvm, float* __restrict__ Cvp, int l)
{
    extern __shared__ float smf[];
    float* SAf = smf;                 // [128][ASTR] fp32 A
    float* SWf = smf + NN*ASTR;       // [128][BSTR] fp32 W

    int p = blockIdx.y;
    const float* A; const float* W; const float* bias; float* C;
    if      (p == 0) { A = Am; W = Wq  + (size_t)l*HSQ; bias = bq  + l*HH; C = Cq;  }
    else if (p == 1) { A = Am; W = Wk  + (size_t)l*HSQ; bias = bk  + l*HH; C = Ck;  }
    else if (p == 2) { A = Am; W = Wvm + (size_t)l*HSQ; bias = bvm + l*HH; C = Cvm; }
    else             { A = Ap; W = Wvp + (size_t)l*HSQ; bias = bvp + l*HH; C = Cvp; }

    int tid = threadIdx.x;
    int wid = tid >> 5, lane = tid & 31;
    int gid = lane >> 2, tig = lane & 3;
    int wm = (wid & 3) * 32, wn = (wid >> 2) * 32;
    size_t m0 = (size_t)blockIdx.x * 128;

    const float4* Ag = (const float4*)(A + m0*HH);
    const float4* Wg = (const float4*)W;
#pragma unroll
    for (int it = 0; it < 8; it++) {
        int idx = tid + 512*it;
        int r = idx >> 5, c = (idx & 31) * 4;
        *(float4*)(SAf + r*ASTR + c) = Ag[idx];
        *(float4*)(SWf + r*BSTR + c) = Wg[idx];
    }
    __syncthreads();

    float acc[2][4][4];
#pragma unroll
    for (int i = 0; i < 2; i++)
#pragma unroll
        for (int j = 0; j < 4; j++)
#pragma unroll
            for (int q = 0; q < 4; q++) acc[i][j][q] = 0.f;

#pragma unroll
    for (int k0 = 0; k0 < HH; k0 += 8) {
        uint32_t ah[2][4], al[2][4];
#pragma unroll
        for (int mt = 0; mt < 2; mt++) {
            int rb = wm + mt*16;
            split3(SAf[(rb + gid    )*ASTR + k0 + tig    ], ah[mt][0], al[mt][0]);
            split3(SAf[(rb + gid + 8)*ASTR + k0 + tig    ], ah[mt][1], al[mt][1]);
            split3(SAf[(rb + gid    )*ASTR + k0 + tig + 4], ah[mt][2], al[mt][2]);
            split3(SAf[(rb + gid + 8)*ASTR + k0 + tig + 4], ah[mt][3], al[mt][3]);
        }
#pragma unroll
        for (int nt = 0; nt < 4; nt++) {
            int nb = wn + nt*8;
            uint32_t bh0, bl0, bh1, bl1;
            split3(SWf[(k0 + tig    )*BSTR + nb + gid], bh0, bl0);
            split3(SWf[(k0 + tig + 4)*BSTR + nb + gid], bh1, bl1);
            mma3x(acc[0][nt], acc[1][nt], ah[0], al[0], ah[1], al[1], bh0, bh1, bl0, bl1);
        }
    }

#pragma unroll
    for (int mt = 0; mt < 2; mt++) {
        int r0 = (int)m0 + wm + mt*16 + gid;
#pragma unroll
        for (int nt = 0; nt < 4; nt++) {
            int c = wn + nt*8 + 2*tig;
            float b0 = __ldg(bias + c), b1 = __ldg(bias + c + 1);
            *(float2*)(C + (size_t)r0*HH + c)       = make_float2(acc[mt][nt][0] + b0, acc[mt][nt][1] + b1);
            *(float2*)(C + (size_t)(r0+8)*HH + c)   = make_float2(acc[mt][nt][2] + b0, acc[mt][nt][3] + b1);
        }
    }
}

// ---------------- K2: per-molecule attention layer (3xTF32, 512 thr) ----------------
__global__ __launch_bounds__(512) void k_attn(
    const int* __restrict__ ei, const float* __restrict__ ea,
    const float* __restrict__ We, const float* __restrict__ be,
    const float* __restrict__ ds,
    const float* __restrict__ lng, const float* __restrict__ lnb,
    int l)
{
    extern __shared__ float sm[];
    float* SA = sm;                              // [128][ASTR] Q / residual
    float* SB = sm + NN*ASTR;                    // [128][BSTR] K (stride ASTR) / V (stride BSTR)
    float* SS = sm + NN*ASTR + NN*BSTR;          // [128][ASTR] scores / probs

    int b = blockIdx.x, tid = threadIdx.x;
    int wid = tid >> 5, lane = tid & 31;
    int gid = lane >> 2, tig = lane & 3;
    int wm = (wid & 3) * 32, wn = (wid >> 2) * 32;
    size_t base = (size_t)b*NH;

    // ---- load Q, K; zero SS ----
#pragma unroll
    for (int it = 0; it < 8; it++) {
        int idx = tid + 512*it;
        int r = idx >> 5, c = (idx & 31) * 4;
        *(float4*)(SA + r*ASTR + c) = *(const float4*)(g_q + base + (size_t)r*HH + c);
        *(float4*)(SB + r*ASTR + c) = *(const float4*)(g_k + base + (size_t)r*HH + c);
    }
    for (int i = tid; i < NN*ASTR/4; i += 512) ((float4*)SS)[i] = make_float4(0.f, 0.f, 0.f, 0.f);
    __syncthreads();

    // ---- edge bias scatter into SS ----
    {
        float w0 = We[l*4+0], w1 = We[l*4+1], w2 = We[l*4+2], w3 = We[l*4+3];
        float beL = be[l], dsL = ds[l];
        for (int e = tid; e < EE; e += 512) {
            int i0 = ei[(size_t)b*2*EE + e];
            int j0 = ei[(size_t)b*2*EE + EE + e];
            const float* a = ea + ((size_t)b*EE + e)*EDIM;
            float v = fmaf(a[0], w0, fmaf(a[1], w1, fmaf(a[2], w2, fmaf(a[3], w3, beL)))) + dsL*a[0];
            atomicAdd(&SS[i0*ASTR + j0], v);
        }
    }
    __syncthreads();

    // ---- scores = Q @ K^T * scale + bias ----
    {
        float acc[2][4][4];
#pragma unroll
        for (int i = 0; i < 2; i++)
#pragma unroll
            for (int j = 0; j < 4; j++)
#pragma unroll
                for (int q = 0; q < 4; q++) acc[i][j][q] = 0.f;
#pragma unroll
        for (int k0 = 0; k0 < HH; k0 += 8) {
            uint32_t ah[2][4], al[2][4];
#pragma unroll
            for (int mt = 0; mt < 2; mt++) {
                int rb = wm + mt*16;
                split3(SA[(rb + gid    )*ASTR + k0 + tig    ], ah[mt][0], al[mt][0]);
                split3(SA[(rb + gid + 8)*ASTR + k0 + tig    ], ah[mt][1], al[mt][1]);
                split3(SA[(rb + gid    )*ASTR + k0 + tig + 4], ah[mt][2], al[mt][2]);
                split3(SA[(rb + gid + 8)*ASTR + k0 + tig + 4], ah[mt][3], al[mt][3]);
            }
#pragma unroll
            for (int nt = 0; nt < 4; nt++) {
                int nb = wn + nt*8;
                uint32_t bh0, bl0, bh1, bl1;
                split3(SB[(nb + gid)*ASTR + k0 + tig    ], bh0, bl0);
                split3(SB[(nb + gid)*ASTR + k0 + tig + 4], bh1, bl1);
                mma3x(acc[0][nt], acc[1][nt], ah[0], al[0], ah[1], al[1], bh0, bh1, bl0, bl1);
            }
        }
        const float scale = 0.08838834764831845f;
#pragma unroll
        for (int mt = 0; mt < 2; mt++) {
            int r0 = wm + mt*16 + gid;
#pragma unroll
            for (int nt = 0; nt < 4; nt++) {
                int c = wn + nt*8 + 2*tig;
                SS[r0*ASTR + c]       = fmaf(acc[mt][nt][0], scale, SS[r0*ASTR + c]);
                SS[r0*ASTR + c + 1]   = fmaf(acc[mt][nt][1], scale, SS[r0*ASTR + c + 1]);
                SS[(r0+8)*ASTR + c]   = fmaf(acc[mt][nt][2], scale, SS[(r0+8)*ASTR + c]);
                SS[(r0+8)*ASTR + c+1] = fmaf(acc[mt][nt][3], scale, SS[(r0+8)*ASTR + c + 1]);
            }
        }
    }
    __syncthreads();

    // ---- softmax: 4 threads per row ----
    {
        int row = tid >> 2, qtr = tid & 3;
        float* rp = SS + row*ASTR + 32*qtr;
        float m = -1e30f;
#pragma unroll
        for (int j = 0; j < 8; j++) {
            float4 v = *(const float4*)(rp + 4*j);
            m = fmaxf(m, fmaxf(fmaxf(v.x, v.y), fmaxf(v.z, v.w)));
        }
        m = fmaxf(m, __shfl_xor_sync(0xffffffffu, m, 1));
        m = fmaxf(m, __shfl_xor_sync(0xffffffffu, m, 2));
        float s = 0.f;
#pragma unroll
        for (int j = 0; j < 8; j++) {
            float4 v = *(float4*)(rp + 4*j);
            v.x = __expf(v.x - m); v.y = __expf(v.y - m);
            v.z = __expf(v.z - m); v.w = __expf(v.w - m);
            s += v.x + v.y + v.z + v.w;
            *(float4*)(rp + 4*j) = v;
        }
        s += __shfl_xor_sync(0xffffffffu, s, 1);
        s += __shfl_xor_sync(0xffffffffu, s, 2);
        float inv = 1.f / s;
#pragma unroll
        for (int j = 0; j < 8; j++) {
            float4 v = *(float4*)(rp + 4*j);
            v.x *= inv; v.y *= inv; v.z *= inv; v.w *= inv;
            *(float4*)(rp + 4*j) = v;
        }
    }
    __syncthreads();

    // ================== two AV passes: vm (with LN) then vp ==================
#pragma unroll 1
    for (int pass = 0; pass < 2; pass++) {
        const float* Vsrc = pass == 0 ? g_vm : g_vp;
        const float* Rsrc = pass == 0 ? g_mag : g_ph;
        float*       Rdst = pass == 0 ? g_mag : g_ph;

#pragma unroll
        for (int it = 0; it < 8; it++) {
            int idx = tid + 512*it;
            int r = idx >> 5, c = (idx & 31) * 4;
            *(float4*)(SB + r*BSTR + c) = *(const float4*)(Vsrc + base + (size_t)r*HH + c);
            *(float4*)(SA + r*ASTR + c) = *(const float4*)(Rsrc + base + (size_t)r*HH + c);
        }
        __syncthreads();

        {
            float acc[2][4][4];
#pragma unroll
            for (int i = 0; i < 2; i++)
#pragma unroll
                for (int j = 0; j < 4; j++)
#pragma unroll
                    for (int q = 0; q < 4; q++) acc[i][j][q] = 0.f;
#pragma unroll
            for (int k0 = 0; k0 < NN; k0 += 8) {
                uint32_t ah[2][4], al[2][4];
#pragma unroll
                for (int mt = 0; mt < 2; mt++) {
                    int rb = wm + mt*16;
                    split3(SS[(rb + gid    )*ASTR + k0 + tig    ], ah[mt][0], al[mt][0]);
                    split3(SS[(rb + gid + 8)*ASTR + k0 + tig    ], ah[mt][1], al[mt][1]);
                    split3(SS[(rb + gid    )*ASTR + k0 + tig + 4], ah[mt][2], al[mt][2]);
                    split3(SS[(rb + gid + 8)*ASTR + k0 + tig + 4], ah[mt][3], al[mt][3]);
                }
#pragma unroll
                for (int nt = 0; nt < 4; nt++) {
                    int nb = wn + nt*8;
                    uint32_t bh0, bl0, bh1, bl1;
                    split3(SB[(k0 + tig    )*BSTR + nb + gid], bh0, bl0);
                    split3(SB[(k0 + tig + 4)*BSTR + nb + gid], bh1, bl1);
                    mma3x(acc[0][nt], acc[1][nt], ah[0], al[0], ah[1], al[1], bh0, bh1, bl0, bl1);
                }
            }
#pragma unroll
            for (int mt = 0; mt < 2; mt++) {
                int r0 = wm + mt*16 + gid;
#pragma unroll
                for (int nt = 0; nt < 4; nt++) {
                    int c = wn + nt*8 + 2*tig;
                    float2 v0 = *(float2*)(SA + r0*ASTR + c);
                    float2 v1 = *(float2*)(SA + (r0+8)*ASTR + c);
                    v0.x += acc[mt][nt][0]; v0.y += acc[mt][nt][1];
                    v1.x += acc[mt][nt][2]; v1.y += acc[mt][nt][3];
                    *(float2*)(SA + r0*ASTR + c)     = v0;
                    *(float2*)(SA + (r0+8)*ASTR + c) = v1;
                }
            }
        }
        __syncthreads();

        if (pass == 0) {
            // LayerNorm rows of SA (magnitude only): 4 threads per row
            int row = tid >> 2, qtr = tid & 3;
            float* rp = SA + row*ASTR + 32*qtr;
            float su = 0.f;
#pragma unroll
            for (int j = 0; j < 8; j++) {
                float4 v = *(const float4*)(rp + 4*j);
                su += v.x + v.y + v.z + v.w;
            }
            su += __shfl_xor_sync(0xffffffffu, su, 1);
            su += __shfl_xor_sync(0xffffffffu, su, 2);
            float mu = su * (1.f/128.f);
            float var = 0.f;
#pragma unroll
            for (int j = 0; j < 8; j++) {
                float4 v = *(const float4*)(rp + 4*j);
                float d0 = v.x - mu, d1 = v.y - mu, d2 = v.z - mu, d3 = v.w - mu;
                var = fmaf(d0, d0, var); var = fmaf(d1, d1, var);
                var = fmaf(d2, d2, var); var = fmaf(d3, d3, var);
            }
            var += __shfl_xor_sync(0xffffffffu, var, 1);
            var += __shfl_xor_sync(0xffffffffu, var, 2);
            float rs = rsqrtf(var * (1.f/128.f) + 1e-5f);
            const float* gp  = lng + l*HH + 32*qtr;
            const float* bp2 = lnb + l*HH + 32*qtr;
#pragma unroll
            for (int j = 0; j < 8; j++) {
                float4 v = *(float4*)(rp + 4*j);
                float4 g = *(const float4*)(gp + 4*j);
                float4 be2 = *(const float4*)(bp2 + 4*j);
                v.x = fmaf(g.x, (v.x - mu)*rs, be2.x);
                v.y = fmaf(g.y, (v.y - mu)*rs, be2.y);
                v.z = fmaf(g.z, (v.z - mu)*rs, be2.z);
                v.w = fmaf(g.w, (v.w - mu)*rs, be2.w);
                *(float4*)(rp + 4*j) = v;
            }
            __syncthreads();
        }

#pragma unroll
        for (int it = 0; it < 8; it++) {
            int idx = tid + 512*it;
            int r = idx >> 5, c = (idx & 31) * 4;
            *(float4*)(Rdst + base + (size_t)r*HH + c) = *(const float4*)(SA + r*ASTR + c);
        }
        __syncthreads();
    }
}

// ---------------- K3: head ----------------
__global__ void k_head(const float* __restrict__ rpW, const float* __restrict__ rpb,
                       const float* __restrict__ h1W, const float* __restrict__ h1b,
                       const float* __restrict__ h2W, const float* __restrict__ h2b,
                       float* __restrict__ out)
{
    int b = blockIdx.x, t = threadIdx.x;
    __shared__ float sS[2*HH];
    __shared__ float sp[2*HH];
    __shared__ float sr[HH];
    size_t base = (size_t)b*NH;

    float ac = 0.f, as = 0.f;
    for (int n = 0; n < NN; n++) {
        float m = g_mag[base + (size_t)n*HH + t];
        float p = g_ph [base + (size_t)n*HH + t];
        float si, co;
        sincosf(p, &si, &co);
        ac = fmaf(m, co, ac);
        as = fmaf(m, si, as);
    }
    sS[t] = ac; sS[HH + t] = as;
    __syncthreads();

    float d = 0.f;
    for (int c = 0; c < 2*HH; c++) d = fmaf(sS[c], rpW[(size_t)c*HH + t], d);
    float sumr = d + 128.f * rpb[t];
    sp[t]      = sumr * (1.f/128.f);
    sp[HH + t] = sumr;
    __syncthreads();

    float hv = h1b[t];
    for (int c = 0; c < 2*HH; c++) hv = fmaf(sp[c], h1W[(size_t)c*HH + t], hv);
    hv = hv / (1.f + expf(-hv));
    sr[t] = hv * h2W[t];
    __syncthreads();

    for (int s = 64; s >= 1; s >>= 1) {
        if (t < s) sr[t] += sr[t + s];
        __syncthreads();
    }
    if (t == 0) out[b] = sr[0] + h2b[0];
}

// ---------------- launch ----------------
extern "C" void kernel_launch(void* const* d_in, const int* in_sizes, int n_in,
                              void* d_out, int out_size)
{
    const float* at   = (const float*)d_in[0];
    const float* sph  = (const float*)d_in[1];
    const int*   ei   = (const int*)  d_in[2];
    const float* ea   = (const float*)d_in[3];
    const float* Wm   = (const float*)d_in[4];
    const float* bm   = (const float*)d_in[5];
    const float* Wp   = (const float*)d_in[6];
    const float* bp   = (const float*)d_in[7];
    const float* Wq   = (const float*)d_in[8];
    const float* bq   = (const float*)d_in[9];
    const float* Wk   = (const float*)d_in[10];
    const float* bk   = (const float*)d_in[11];
    const float* Wvm  = (const float*)d_in[12];
    const float* bvm  = (const float*)d_in[13];
    const float* Wvp  = (const float*)d_in[14];
    const float* bvp  = (const float*)d_in[15];
    const float* We   = (const float*)d_in[16];
    const float* be   = (const float*)d_in[17];
    const float* ds   = (const float*)d_in[18];
    const float* lng  = (const float*)d_in[19];
    const float* lnb  = (const float*)d_in[20];
    const float* rpW  = (const float*)d_in[21];
    const float* rpb  = (const float*)d_in[22];
    const float* h1W  = (const float*)d_in[23];
    const float* h1b  = (const float*)d_in[24];
    const float* h2W  = (const float*)d_in[25];
    const float* h2b  = (const float*)d_in[26];
    float* out = (float*)d_out;

    void *p_mag, *p_ph, *p_q, *p_k, *p_vm, *p_vp;
    cudaGetSymbolAddress(&p_mag, g_mag);
    cudaGetSymbolAddress(&p_ph,  g_ph);
    cudaGetSymbolAddress(&p_q,   g_q);
    cudaGetSymbolAddress(&p_k,   g_k);
    cudaGetSymbolAddress(&p_vm,  g_vm);
    cudaGetSymbolAddress(&p_vp,  g_vp);

    size_t proj_smem = (size_t)(NN*ASTR + NN*BSTR) * 4;              // 137216
    size_t attn_smem = (size_t)(NN*ASTR + NN*BSTR + NN*ASTR) * 4;    // 204800
    cudaFuncSetAttribute(k_proj_mma, cudaFuncAttributeMaxDynamicSharedMemorySize, (int)proj_smem);
    cudaFuncSetAttribute(k_attn,     cudaFuncAttributeMaxDynamicSharedMemorySize, (int)attn_smem);

    k_embed<<<BB, 128>>>(at, sph, Wm, bm, Wp, bp);

    for (int l = 0; l < LL; l++) {
        dim3 pg(1024, 4);
        k_proj_mma<<<pg, 512, proj_smem>>>((const float*)p_mag, (const float*)p_ph,
                                           Wq, bq, Wk, bk, Wvm, bvm, Wvp, bvp,
                                           (float*)p_q, (float*)p_k, (float*)p_vm, (float*)p_vp, l);
        k_attn<<<BB, 512, attn_smem>>>(ei, ea, We, be, ds, lng, lnb, l);
    }

    k_head<<<BB, 128>>>(rpW, rpb, h1W, h1b, h2W, h2b, out);
}

// round 8
// speedup vs baseline: 1.6744x; 1.0494x over previous
#include <cuda_runtime.h>
#include <math.h>
#include <stdint.h>

#define BB   1024
#define NN   128
#define EE   1024
#define HH   128
#define LL   4
#define INDIM 16
#define DIN  19
#define EDIM 4
#define NH   (NN*HH)      // 16384
#define HSQ  (HH*HH)      // 16384

#define ASTR 132          // stride (words) for A-pattern smem buffers
#define BSTR 136          // stride (words) for B-pattern fp32 smem buffers
#define W2STR 132         // stride (float2) for pre-split W tiles

// ---------------- device scratch ----------------
__device__ float g_mag[(size_t)BB*NH];
__device__ float g_ph [(size_t)BB*NH];
__device__ float g_q  [(size_t)BB*NH];
__device__ float g_k  [(size_t)BB*NH];
__device__ float g_vm [(size_t)BB*NH];
__device__ float g_vp [(size_t)BB*NH];
__device__ float2 g_w2[(size_t)LL*4*HSQ];   // pre-split weights (hi, lo)

// ---------------- helpers ----------------
// truncation-based 3xTF32 split: hi = x masked to tf32 mantissa, lo = exact remainder.
// 2 ops (LOP3 + FSUB) on different pipes; MMA HW truncates lo to tf32 itself.
__device__ __forceinline__ void splitT(float x, uint32_t& hi, uint32_t& lo) {
    uint32_t h = __float_as_uint(x) & 0xffffe000u;
    hi = h;
    lo = __float_as_uint(x - __uint_as_float(h));
}
__device__ __forceinline__ void mma8(float* c, const uint32_t* a, uint32_t b0, uint32_t b1) {
    asm volatile("mma.sync.aligned.m16n8k8.row.col.f32.tf32.tf32.f32 "
        "{%0,%1,%2,%3}, {%4,%5,%6,%7}, {%8,%9}, {%0,%1,%2,%3};"
        : "+f"(c[0]), "+f"(c[1]), "+f"(c[2]), "+f"(c[3])
        : "r"(a[0]), "r"(a[1]), "r"(a[2]), "r"(a[3]), "r"(b0), "r"(b1));
}
// 3xTF32 update for a pair of m-tiles sharing one B fragment: 6 mma
__device__ __forceinline__ void mma3x(float* c0, float* c1,
                                      const uint32_t* ah0, const uint32_t* al0,
                                      const uint32_t* ah1, const uint32_t* al1,
                                      uint32_t bh0, uint32_t bh1, uint32_t bl0, uint32_t bl1) {
    mma8(c0, ah0, bh0, bh1);
    mma8(c1, ah1, bh0, bh1);
    mma8(c0, ah0, bl0, bl1);
    mma8(c1, ah1, bl0, bl1);
    mma8(c0, al0, bh0, bh1);
    mma8(c1, al1, bh0, bh1);
}

// ---------------- K0: complex embedding ----------------
__global__ void k_embed(const float* __restrict__ at, const float* __restrict__ sph,
                        const float* __restrict__ Wm, const float* __restrict__ bm,
                        const float* __restrict__ Wp, const float* __restrict__ bp)
{
    int b = blockIdx.x, t = threadIdx.x;
    __shared__ float sx[NN][20];
    for (int i = t; i < NN*DIN; i += blockDim.x) {
        int n = i / DIN, d = i % DIN;
        sx[n][d] = (d < INDIM) ? at[((size_t)b*NN + n)*INDIM + d]
                               : sph[((size_t)b*NN + n)*3 + (d - INDIM)];
    }
    __syncthreads();
    float wm[DIN], wp[DIN];
#pragma unroll
    for (int d = 0; d < DIN; d++) { wm[d] = Wm[d*HH + t]; wp[d] = Wp[d*HH + t]; }
    float bmv = bm[t], bpv = bp[t];
    size_t base = (size_t)b*NH;
    for (int n = 0; n < NN; n++) {
        float am = bmv, ap = bpv;
#pragma unroll
        for (int d = 0; d < DIN; d++) { float x = sx[n][d]; am = fmaf(x, wm[d], am); ap = fmaf(x, wp[d], ap); }
        g_mag[base + (size_t)n*HH + t] = am;
        g_ph [base + (size_t)n*HH + t] = ap;
    }
}

// ---------------- K_ws: pre-split all 16 weight matrices into (hi, lo) ----------------
__global__ void k_wsplit(const float* __restrict__ Wq, const float* __restrict__ Wk,
                         const float* __restrict__ Wvm, const float* __restrict__ Wvp)
{
    int m = blockIdx.x;           // l*4 + p
    int l = m >> 2, p = m & 3;
    const float* W = (p == 0 ? Wq : p == 1 ? Wk : p == 2 ? Wvm : Wvp) + (size_t)l*HSQ;
    float2* O = g_w2 + (size_t)m*HSQ;
    for (int i = threadIdx.x; i < HSQ; i += blockDim.x) {
        float w = W[i];
        float h = __uint_as_float(__float_as_uint(w) & 0xffffe000u);
        O[i] = make_float2(h, w - h);
    }
}

// ---------------- K1: projection GEMM, 3xTF32, pre-split W (512 thr) ----------------
// grid = (1024, 4): y picks {q,k,vm,vp}. CTA computes 128x128, K=128.
__global__ __launch_bounds__(512) void k_proj_mma(
    const float* __restrict__ Am, const float* __restrict__ Ap,
    const float* __restrict__ bq, const float* __restrict__ bk,
    const float* __restrict__ bvm, const float* __restrict__ bvp,
    float* __restrict__ Cq, float* __restrict__ Ck,
    float* __restrict__ Cvm, float* __restrict__ Cvp, int l)
{
    extern __shared__ float smf[];
    float*  SAf = smf;                           // [128][ASTR] fp32 A
    float2* SW2 = (float2*)(smf + NN*ASTR);      // [128][W2STR] (hi,lo) W

    int p = blockIdx.y;
    const float* A    = (p == 3) ? Ap : Am;
    const float2* W2  = g_w2 + (size_t)(l*4 + p)*HSQ;
    const float* bias = (p == 0 ? bq : p == 1 ? bk : p == 2 ? bvm : bvp) + l*HH;
    float*       C    = (p == 0 ? Cq : p == 1 ? Ck : p == 2 ? Cvm : Cvp);

    int tid = threadIdx.x;
    int wid = tid >> 5, lane = tid & 31;
    int gid = lane >> 2, tig = lane & 3;
    int wm = (wid & 3) * 32, wn = (wid >> 2) * 32;
    size_t m0 = (size_t)blockIdx.x * 128;

    const float4* Ag = (const float4*)(A + m0*HH);
#pragma unroll
    for (int it = 0; it < 8; it++) {
        int idx = tid + 512*it;
        int r = idx >> 5, c = (idx & 31) * 4;
        *(float4*)(SAf + r*ASTR + c) = Ag[idx];
    }
    // W: 16384 float2 = 8192 float4 chunks (2 float2 each)
    const float4* Wg = (const float4*)W2;
#pragma unroll
    for (int it = 0; it < 16; it++) {
        int idx = tid + 512*it;
        int r = idx >> 6, c2 = (idx & 63) * 2;   // float2 column
        *(float4*)(SW2 + r*W2STR + c2) = Wg[idx];
    }
    __syncthreads();

    float acc[2][4][4];
#pragma unroll
    for (int i = 0; i < 2; i++)
#pragma unroll
        for (int j = 0; j < 4; j++)
#pragma unroll
            for (int q = 0; q < 4; q++) acc[i][j][q] = 0.f;

#pragma unroll
    for (int k0 = 0; k0 < HH; k0 += 8) {
        uint32_t ah[2][4], al[2][4];
#pragma unroll
        for (int mt = 0; mt < 2; mt++) {
            int rb = wm + mt*16;
            splitT(SAf[(rb + gid    )*ASTR + k0 + tig    ], ah[mt][0], al[mt][0]);
            splitT(SAf[(rb + gid + 8)*ASTR + k0 + tig    ], ah[mt][1], al[mt][1]);
            splitT(SAf[(rb + gid    )*ASTR + k0 + tig + 4], ah[mt][2], al[mt][2]);
            splitT(SAf[(rb + gid + 8)*ASTR + k0 + tig + 4], ah[mt][3], al[mt][3]);
        }
#pragma unroll
        for (int nt = 0; nt < 4; nt++) {
            int nb = wn + nt*8;
            float2 b0 = SW2[(k0 + tig    )*W2STR + nb + gid];   // LDS.64 (hi,lo)
            float2 b1 = SW2[(k0 + tig + 4)*W2STR + nb + gid];
            mma3x(acc[0][nt], acc[1][nt], ah[0], al[0], ah[1], al[1],
                  __float_as_uint(b0.x), __float_as_uint(b1.x),
                  __float_as_uint(b0.y), __float_as_uint(b1.y));
        }
    }

#pragma unroll
    for (int mt = 0; mt < 2; mt++) {
        int r0 = (int)m0 + wm + mt*16 + gid;
#pragma unroll
        for (int nt = 0; nt < 4; nt++) {
            int c = wn + nt*8 + 2*tig;
            float b0 = __ldg(bias + c), b1 = __ldg(bias + c + 1);
            *(float2*)(C + (size_t)r0*HH + c)       = make_float2(acc[mt][nt][0] + b0, acc[mt][nt][1] + b1);
            *(float2*)(C + (size_t)(r0+8)*HH + c)   = make_float2(acc[mt][nt][2] + b0, acc[mt][nt][3] + b1);
        }
    }
}

// ---------------- K2: per-molecule attention layer (3xTF32, 512 thr) ----------------
__global__ __launch_bounds__(512) void k_attn(
    const int* __restrict__ ei, const float* __restrict__ ea,
    const float* __restrict__ We, const float* __restrict__ be,
    const float* __restrict__ ds,
    const float* __restrict__ lng, const float* __restrict__ lnb,
    int l)
{
    extern __shared__ float sm[];
    float* SA = sm;                              // [128][ASTR] Q / residual
    float* SB = sm + NN*ASTR;                    // [128][BSTR] K (stride ASTR) / V (stride BSTR)
    float* SS = sm + NN*ASTR + NN*BSTR;          // [128][ASTR] scores / probs

    int b = blockIdx.x, tid = threadIdx.x;
    int wid = tid >> 5, lane = tid & 31;
    int gid = lane >> 2, tig = lane & 3;
    int wm = (wid & 3) * 32, wn = (wid >> 2) * 32;
    size_t base = (size_t)b*NH;

    // ---- load Q, K; zero SS ----
#pragma unroll
    for (int it = 0; it < 8; it++) {
        int idx = tid + 512*it;
        int r = idx >> 5, c = (idx & 31) * 4;
        *(float4*)(SA + r*ASTR + c) = *(const float4*)(g_q + base + (size_t)r*HH + c);
        *(float4*)(SB + r*ASTR + c) = *(const float4*)(g_k + base + (size_t)r*HH + c);
    }
    for (int i = tid; i < NN*ASTR/4; i += 512) ((float4*)SS)[i] = make_float4(0.f, 0.f, 0.f, 0.f);
    __syncthreads();

    // ---- edge bias scatter into SS ----
    {
        float w0 = We[l*4+0], w1 = We[l*4+1], w2 = We[l*4+2], w3 = We[l*4+3];
        float beL = be[l], dsL = ds[l];
        for (int e = tid; e < EE; e += 512) {
            int i0 = ei[(size_t)b*2*EE + e];
            int j0 = ei[(size_t)b*2*EE + EE + e];
            const float* a = ea + ((size_t)b*EE + e)*EDIM;
            float v = fmaf(a[0], w0, fmaf(a[1], w1, fmaf(a[2], w2, fmaf(a[3], w3, beL)))) + dsL*a[0];
            atomicAdd(&SS[i0*ASTR + j0], v);
        }
    }
    __syncthreads();

    // ---- scores = Q @ K^T * scale + bias ----
    {
        float acc[2][4][4];
#pragma unroll
        for (int i = 0; i < 2; i++)
#pragma unroll
            for (int j = 0; j < 4; j++)
#pragma unroll
                for (int q = 0; q < 4; q++) acc[i][j][q] = 0.f;
#pragma unroll
        for (int k0 = 0; k0 < HH; k0 += 8) {
            uint32_t ah[2][4], al[2][4];
#pragma unroll
            for (int mt = 0; mt < 2; mt++) {
                int rb = wm + mt*16;
                splitT(SA[(rb + gid    )*ASTR + k0 + tig    ], ah[mt][0], al[mt][0]);
                splitT(SA[(rb + gid + 8)*ASTR + k0 + tig    ], ah[mt][1], al[mt][1]);
                splitT(SA[(rb + gid    )*ASTR + k0 + tig + 4], ah[mt][2], al[mt][2]);
                splitT(SA[(rb + gid + 8)*ASTR + k0 + tig + 4], ah[mt][3], al[mt][3]);
            }
#pragma unroll
            for (int nt = 0; nt < 4; nt++) {
                int nb = wn + nt*8;
                uint32_t bh0, bl0, bh1, bl1;
                splitT(SB[(nb + gid)*ASTR + k0 + tig    ], bh0, bl0);
                splitT(SB[(nb + gid)*ASTR + k0 + tig + 4], bh1, bl1);
                mma3x(acc[0][nt], acc[1][nt], ah[0], al[0], ah[1], al[1], bh0, bh1, bl0, bl1);
            }
        }
        const float scale = 0.08838834764831845f;
#pragma unroll
        for (int mt = 0; mt < 2; mt++) {
            int r0 = wm + mt*16 + gid;
#pragma unroll
            for (int nt = 0; nt < 4; nt++) {
                int c = wn + nt*8 + 2*tig;
                SS[r0*ASTR + c]       = fmaf(acc[mt][nt][0], scale, SS[r0*ASTR + c]);
                SS[r0*ASTR + c + 1]   = fmaf(acc[mt][nt][1], scale, SS[r0*ASTR + c + 1]);
                SS[(r0+8)*ASTR + c]   = fmaf(acc[mt][nt][2], scale, SS[(r0+8)*ASTR + c]);
                SS[(r0+8)*ASTR + c+1] = fmaf(acc[mt][nt][3], scale, SS[(r0+8)*ASTR + c + 1]);
            }
        }
    }
    __syncthreads();

    // ---- softmax: 4 threads per row ----
    {
        int row = tid >> 2, qtr = tid & 3;
        float* rp = SS + row*ASTR + 32*qtr;
        float m = -1e30f;
#pragma unroll
        for (int j = 0; j < 8; j++) {
            float4 v = *(const float4*)(rp + 4*j);
            m = fmaxf(m, fmaxf(fmaxf(v.x, v.y), fmaxf(v.z, v.w)));
        }
        m = fmaxf(m, __shfl_xor_sync(0xffffffffu, m, 1));
        m = fmaxf(m, __shfl_xor_sync(0xffffffffu, m, 2));
        float s = 0.f;
#pragma unroll
        for (int j = 0; j < 8; j++) {
            float4 v = *(float4*)(rp + 4*j);
            v.x = __expf(v.x - m); v.y = __expf(v.y - m);
            v.z = __expf(v.z - m); v.w = __expf(v.w - m);
            s += v.x + v.y + v.z + v.w;
            *(float4*)(rp + 4*j) = v;
        }
        s += __shfl_xor_sync(0xffffffffu, s, 1);
        s += __shfl_xor_sync(0xffffffffu, s, 2);
        float inv = 1.f / s;
#pragma unroll
        for (int j = 0; j < 8; j++) {
            float4 v = *(float4*)(rp + 4*j);
            v.x *= inv; v.y *= inv; v.z *= inv; v.w *= inv;
            *(float4*)(rp + 4*j) = v;
        }
    }
    __syncthreads();

    // ================== two AV passes: vm (with LN) then vp ==================
#pragma unroll 1
    for (int pass = 0; pass < 2; pass++) {
        const float* Vsrc = pass == 0 ? g_vm : g_vp;
        const float* Rsrc = pass == 0 ? g_mag : g_ph;
        float*       Rdst = pass == 0 ? g_mag : g_ph;

#pragma unroll
        for (int it = 0; it < 8; it++) {
            int idx = tid + 512*it;
            int r = idx >> 5, c = (idx & 31) * 4;
            *(float4*)(SB + r*BSTR + c) = *(const float4*)(Vsrc + base + (size_t)r*HH + c);
            *(float4*)(SA + r*ASTR + c) = *(const float4*)(Rsrc + base + (size_t)r*HH + c);
        }
        __syncthreads();

        {
            float acc[2][4][4];
#pragma unroll
            for (int i = 0; i < 2; i++)
#pragma unroll
                for (int j = 0; j < 4; j++)
#pragma unroll
                    for (int q = 0; q < 4; q++) acc[i][j][q] = 0.f;
#pragma unroll
            for (int k0 = 0; k0 < NN; k0 += 8) {
                uint32_t ah[2][4], al[2][4];
#pragma unroll
                for (int mt = 0; mt < 2; mt++) {
                    int rb = wm + mt*16;
                    splitT(SS[(rb + gid    )*ASTR + k0 + tig    ], ah[mt][0], al[mt][0]);
                    splitT(SS[(rb + gid + 8)*ASTR + k0 + tig    ], ah[mt][1], al[mt][1]);
                    splitT(SS[(rb + gid    )*ASTR + k0 + tig + 4], ah[mt][2], al[mt][2]);
                    splitT(SS[(rb + gid + 8)*ASTR + k0 + tig + 4], ah[mt][3], al[mt][3]);
                }
#pragma unroll
                for (int nt = 0; nt < 4; nt++) {
                    int nb = wn + nt*8;
                    uint32_t bh0, bl0, bh1, bl1;
                    splitT(SB[(k0 + tig    )*BSTR + nb + gid], bh0, bl0);
                    splitT(SB[(k0 + tig + 4)*BSTR + nb + gid], bh1, bl1);
                    mma3x(acc[0][nt], acc[1][nt], ah[0], al[0], ah[1], al[1], bh0, bh1, bl0, bl1);
                }
            }
#pragma unroll
            for (int mt = 0; mt < 2; mt++) {
                int r0 = wm + mt*16 + gid;
#pragma unroll
                for (int nt = 0; nt < 4; nt++) {
                    int c = wn + nt*8 + 2*tig;
                    float2 v0 = *(float2*)(SA + r0*ASTR + c);
                    float2 v1 = *(float2*)(SA + (r0+8)*ASTR + c);
                    v0.x += acc[mt][nt][0]; v0.y += acc[mt][nt][1];
                    v1.x += acc[mt][nt][2]; v1.y += acc[mt][nt][3];
                    *(float2*)(SA + r0*ASTR + c)     = v0;
                    *(float2*)(SA + (r0+8)*ASTR + c) = v1;
                }
            }
        }
        __syncthreads();

        if (pass == 0) {
            // LayerNorm rows of SA (magnitude only): 4 threads per row
            int row = tid >> 2, qtr = tid & 3;
            float* rp = SA + row*ASTR + 32*qtr;
            float su = 0.f;
#pragma unroll
            for (int j = 0; j < 8; j++) {
                float4 v = *(const float4*)(rp + 4*j);
                su += v.x + v.y + v.z + v.w;
            }
            su += __shfl_xor_sync(0xffffffffu, su, 1);
            su += __shfl_xor_sync(0xffffffffu, su, 2);
            float mu = su * (1.f/128.f);
            float var = 0.f;
#pragma unroll
            for (int j = 0; j < 8; j++) {
                float4 v = *(const float4*)(rp + 4*j);
                float d0 = v.x - mu, d1 = v.y - mu, d2 = v.z - mu, d3 = v.w - mu;
                var = fmaf(d0, d0, var); var = fmaf(d1, d1, var);
                var = fmaf(d2, d2, var); var = fmaf(d3, d3, var);
            }
            var += __shfl_xor_sync(0xffffffffu, var, 1);
            var += __shfl_xor_sync(0xffffffffu, var, 2);
            float rs = rsqrtf(var * (1.f/128.f) + 1e-5f);
            const float* gp  = lng + l*HH + 32*qtr;
            const float* bp2 = lnb + l*HH + 32*qtr;
#pragma unroll
            for (int j = 0; j < 8; j++) {
                float4 v = *(float4*)(rp + 4*j);
                float4 g = *(const float4*)(gp + 4*j);
                float4 be2 = *(const float4*)(bp2 + 4*j);
                v.x = fmaf(g.x, (v.x - mu)*rs, be2.x);
                v.y = fmaf(g.y, (v.y - mu)*rs, be2.y);
                v.z = fmaf(g.z, (v.z - mu)*rs, be2.z);
                v.w = fmaf(g.w, (v.w - mu)*rs, be2.w);
                *(float4*)(rp + 4*j) = v;
            }
            __syncthreads();
        }

#pragma unroll
        for (int it = 0; it < 8; it++) {
            int idx = tid + 512*it;
            int r = idx >> 5, c = (idx & 31) * 4;
            *(float4*)(Rdst + base + (size_t)r*HH + c) = *(const float4*)(SA + r*ASTR + c);
        }
        __syncthreads();
    }
}

// ---------------- K3: head ----------------
__global__ void k_head(const float* __restrict__ rpW, const float* __restrict__ rpb,
                       const float* __restrict__ h1W, const float* __restrict__ h1b,
                       const float* __restrict__ h2W, const float* __restrict__ h2b,
                       float* __restrict__ out)
{
    int b = blockIdx.x, t = threadIdx.x;
    __shared__ float sS[2*HH];
    __shared__ float sp[2*HH];
    __shared__ float sr[HH];
    size_t base = (size_t)b*NH;

    float ac = 0.f, as = 0.f;
    for (int n = 0; n < NN; n++) {
        float m = g_mag[base + (size_t)n*HH + t];
        float p = g_ph [base + (size_t)n*HH + t];
        float si, co;
        sincosf(p, &si, &co);
        ac = fmaf(m, co, ac);
        as = fmaf(m, si, as);
    }
    sS[t] = ac; sS[HH + t] = as;
    __syncthreads();

    float d = 0.f;
    for (int c = 0; c < 2*HH; c++) d = fmaf(sS[c], rpW[(size_t)c*HH + t], d);
    float sumr = d + 128.f * rpb[t];
    sp[t]      = sumr * (1.f/128.f);
    sp[HH + t] = sumr;
    __syncthreads();

    float hv = h1b[t];
    for (int c = 0; c < 2*HH; c++) hv = fmaf(sp[c], h1W[(size_t)c*HH + t], hv);
    hv = hv / (1.f + expf(-hv));
    sr[t] = hv * h2W[t];
    __syncthreads();

    for (int s = 64; s >= 1; s >>= 1) {
        if (t < s) sr[t] += sr[t + s];
        __syncthreads();
    }
    if (t == 0) out[b] = sr[0] + h2b[0];
}

// ---------------- launch ----------------
extern "C" void kernel_launch(void* const* d_in, const int* in_sizes, int n_in,
                              void* d_out, int out_size)
{
    const float* at   = (const float*)d_in[0];
    const float* sph  = (const float*)d_in[1];
    const int*   ei   = (const int*)  d_in[2];
    const float* ea   = (const float*)d_in[3];
    const float* Wm   = (const float*)d_in[4];
    const float* bm   = (const float*)d_in[5];
    const float* Wp   = (const float*)d_in[6];
    const float* bp   = (const float*)d_in[7];
    const float* Wq   = (const float*)d_in[8];
    const float* bq   = (const float*)d_in[9];
    const float* Wk   = (const float*)d_in[10];
    const float* bk   = (const float*)d_in[11];
    const float* Wvm  = (const float*)d_in[12];
    const float* bvm  = (const float*)d_in[13];
    const float* Wvp  = (const float*)d_in[14];
    const float* bvp  = (const float*)d_in[15];
    const float* We   = (const float*)d_in[16];
    const float* be   = (const float*)d_in[17];
    const float* ds   = (const float*)d_in[18];
    const float* lng  = (const float*)d_in[19];
    const float* lnb  = (const float*)d_in[20];
    const float* rpW  = (const float*)d_in[21];
    const float* rpb  = (const float*)d_in[22];
    const float* h1W  = (const float*)d_in[23];
    const float* h1b  = (const float*)d_in[24];
    const float* h2W  = (const float*)d_in[25];
    const float* h2b  = (const float*)d_in[26];
    float* out = (float*)d_out;

    void *p_mag, *p_ph, *p_q, *p_k, *p_vm, *p_vp;
    cudaGetSymbolAddress(&p_mag, g_mag);
    cudaGetSymbolAddress(&p_ph,  g_ph);
    cudaGetSymbolAddress(&p_q,   g_q);
    cudaGetSymbolAddress(&p_k,   g_k);
    cudaGetSymbolAddress(&p_vm,  g_vm);
    cudaGetSymbolAddress(&p_vp,  g_vp);

    size_t proj_smem = (size_t)NN*ASTR*4 + (size_t)NN*W2STR*8;       // 67584 + 135168 = 202752
    size_t attn_smem = (size_t)(NN*ASTR + NN*BSTR + NN*ASTR) * 4;    // 204800
    cudaFuncSetAttribute(k_proj_mma, cudaFuncAttributeMaxDynamicSharedMemorySize, (int)proj_smem);
    cudaFuncSetAttribute(k_attn,     cudaFuncAttributeMaxDynamicSharedMemorySize, (int)attn_smem);

    k_embed<<<BB, 128>>>(at, sph, Wm, bm, Wp, bp);
    k_wsplit<<<16, 256>>>(Wq, Wk, Wvm, Wvp);

    for (int l = 0; l < LL; l++) {
        dim3 pg(1024, 4);
        k_proj_mma<<<pg, 512, proj_smem>>>((const float*)p_mag, (const float*)p_ph,
                                           bq, bk, bvm, bvp,
                                           (float*)p_q, (float*)p_k, (float*)p_vm, (float*)p_vp, l);
        k_attn<<<BB, 512, attn_smem>>>(ei, ea, We, be, ds, lng, lnb, l);
    }

    k_head<<<BB, 128>>>(rpW, rpb, h1W, h1b, h2W, h2b, out);
}

// round 9
// speedup vs baseline: 2.2759x; 1.3592x over previous
#include <cuda_runtime.h>
#include <math.h>
#include <stdint.h>

#define BB   1024
#define NN   128
#define EE   1024
#define HH   128
#define LL   4
#define INDIM 16
#define DIN  19
#define EDIM 4
#define NH   (NN*HH)      // 16384
#define HSQ  (HH*HH)      // 16384
#define ASTR 132

// ---------------- device scratch ----------------
__device__ float  g_mag[(size_t)BB*NH];
__device__ float  g_ph [(size_t)BB*NH];
__device__ float2 g_m2  [(size_t)LL*HSQ];   // pre-split Wq@Wk^T
__device__ float2 g_wvm2[(size_t)LL*HSQ];   // pre-split Wvm
__device__ float2 g_wvp2[(size_t)LL*HSQ];   // pre-split Wvp
__device__ float  g_u[LL*HH];
__device__ float  g_v[LL*HH];
__device__ float  g_c[LL];

// ---------------- helpers ----------------
__device__ __forceinline__ void splitT(float x, uint32_t& hi, uint32_t& lo) {
    uint32_t h = __float_as_uint(x) & 0xffffe000u;
    hi = h;
    lo = __float_as_uint(x - __uint_as_float(h));
}
__device__ __forceinline__ void mma8(float* c, const uint32_t* a, uint32_t b0, uint32_t b1) {
    asm volatile("mma.sync.aligned.m16n8k8.row.col.f32.tf32.tf32.f32 "
        "{%0,%1,%2,%3}, {%4,%5,%6,%7}, {%8,%9}, {%0,%1,%2,%3};"
        : "+f"(c[0]), "+f"(c[1]), "+f"(c[2]), "+f"(c[3])
        : "r"(a[0]), "r"(a[1]), "r"(a[2]), "r"(a[3]), "r"(b0), "r"(b1));
}
__device__ __forceinline__ void mma3x(float* c0, float* c1,
                                      const uint32_t* ah0, const uint32_t* al0,
                                      const uint32_t* ah1, const uint32_t* al1,
                                      uint32_t bh0, uint32_t bh1, uint32_t bl0, uint32_t bl1) {
    mma8(c0, ah0, bh0, bh1);
    mma8(c1, ah1, bh0, bh1);
    mma8(c0, ah0, bl0, bl1);
    mma8(c1, ah1, bl0, bl1);
    mma8(c0, al0, bh0, bh1);
    mma8(c1, al1, bh0, bh1);
}

// GEMM core: A from smem (stride ASTR) with in-loop split; B by kind:
//   BK=0: smem B^T pattern (B[k][n] = Bf[n][k]), stride ASTR
//   BK=1: smem B  pattern (B[k][n] = Bf[k][n]), stride ASTR
//   BK=2: gmem pre-split float2 [k][n], stride 128
//   BK=3: gmem fp32 [k][n], stride 128, in-loop split
template<int BK>
__device__ __forceinline__ void gemm_core(const float* SA_, const float* Bf, const float2* B2,
                                          int wrm, int wrn, int gid, int tig,
                                          float acc[2][4][4])
{
#pragma unroll
    for (int i = 0; i < 2; i++)
#pragma unroll
        for (int j = 0; j < 4; j++)
#pragma unroll
            for (int q = 0; q < 4; q++) acc[i][j][q] = 0.f;
#pragma unroll
    for (int k0 = 0; k0 < 128; k0 += 8) {
        uint32_t ah[2][4], al[2][4];
#pragma unroll
        for (int mt = 0; mt < 2; mt++) {
            int rb = wrm + mt*16;
            splitT(SA_[(rb + gid    )*ASTR + k0 + tig    ], ah[mt][0], al[mt][0]);
            splitT(SA_[(rb + gid + 8)*ASTR + k0 + tig    ], ah[mt][1], al[mt][1]);
            splitT(SA_[(rb + gid    )*ASTR + k0 + tig + 4], ah[mt][2], al[mt][2]);
            splitT(SA_[(rb + gid + 8)*ASTR + k0 + tig + 4], ah[mt][3], al[mt][3]);
        }
#pragma unroll
        for (int nt = 0; nt < 4; nt++) {
            int nb = wrn + nt*8;
            uint32_t bh0, bl0, bh1, bl1;
            if (BK == 0) {
                splitT(Bf[(nb + gid)*ASTR + k0 + tig    ], bh0, bl0);
                splitT(Bf[(nb + gid)*ASTR + k0 + tig + 4], bh1, bl1);
            } else if (BK == 1) {
                splitT(Bf[(k0 + tig    )*ASTR + nb + gid], bh0, bl0);
                splitT(Bf[(k0 + tig + 4)*ASTR + nb + gid], bh1, bl1);
            } else if (BK == 2) {
                float2 b0 = __ldg(&B2[(k0 + tig    )*128 + nb + gid]);
                float2 b1 = __ldg(&B2[(k0 + tig + 4)*128 + nb + gid]);
                bh0 = __float_as_uint(b0.x); bl0 = __float_as_uint(b0.y);
                bh1 = __float_as_uint(b1.x); bl1 = __float_as_uint(b1.y);
            } else {
                splitT(__ldg(&Bf[(k0 + tig    )*128 + nb + gid]), bh0, bl0);
                splitT(__ldg(&Bf[(k0 + tig + 4)*128 + nb + gid]), bh1, bl1);
            }
            mma3x(acc[0][nt], acc[1][nt], ah[0], al[0], ah[1], al[1], bh0, bh1, bl0, bl1);
        }
    }
}

// ---------------- K0: complex embedding ----------------
__global__ void k_embed(const float* __restrict__ at, const float* __restrict__ sph,
                        const float* __restrict__ Wm, const float* __restrict__ bm,
                        const float* __restrict__ Wp, const float* __restrict__ bp)
{
    int b = blockIdx.x, t = threadIdx.x;
    __shared__ float sx[NN][20];
    for (int i = t; i < NN*DIN; i += blockDim.x) {
        int n = i / DIN, d = i % DIN;
        sx[n][d] = (d < INDIM) ? at[((size_t)b*NN + n)*INDIM + d]
                               : sph[((size_t)b*NN + n)*3 + (d - INDIM)];
    }
    __syncthreads();
    float wm[DIN], wp[DIN];
#pragma unroll
    for (int d = 0; d < DIN; d++) { wm[d] = Wm[d*HH + t]; wp[d] = Wp[d*HH + t]; }
    float bmv = bm[t], bpv = bp[t];
    size_t base = (size_t)b*NH;
    for (int n = 0; n < NN; n++) {
        float am = bmv, ap = bpv;
#pragma unroll
        for (int d = 0; d < DIN; d++) { float x = sx[n][d]; am = fmaf(x, wm[d], am); ap = fmaf(x, wp[d], ap); }
        g_mag[base + (size_t)n*HH + t] = am;
        g_ph [base + (size_t)n*HH + t] = ap;
    }
}

// ---------------- prep: M = Wq@Wk^T (pre-split) ----------------
__global__ void k_prep_m(const float* __restrict__ Wq, const float* __restrict__ Wk)
{
    __shared__ float sq[32][129], sk[32][129];
    int l = blockIdx.x, bi = blockIdx.y, bj = blockIdx.z;
    const float* q = Wq + (size_t)l*HSQ + bi*32*HH;
    const float* k = Wk + (size_t)l*HSQ + bj*32*HH;
    int tid = threadIdx.x;
    for (int i = tid; i < 32*128; i += 256) {
        sq[i >> 7][i & 127] = q[(i >> 7)*HH + (i & 127)];
        sk[i >> 7][i & 127] = k[(i >> 7)*HH + (i & 127)];
    }
    __syncthreads();
    int i = tid >> 3, j0 = (tid & 7) * 4;
    for (int jj = 0; jj < 4; jj++) {
        int j = j0 + jj;
        float s = 0.f;
        for (int n = 0; n < 128; n++) s = fmaf(sq[i][n], sk[j][n], s);
        float h = __uint_as_float(__float_as_uint(s) & 0xffffe000u);
        g_m2[(size_t)l*HSQ + (size_t)(bi*32 + i)*HH + bj*32 + j] = make_float2(h, s - h);
    }
}

// ---------------- prep: u = Wq@bk, v = Wk@bq, c = bq.bk ----------------
__global__ void k_prep_uv(const float* __restrict__ Wq, const float* __restrict__ Wk,
                          const float* __restrict__ bqv, const float* __restrict__ bkv)
{
    int l = blockIdx.x, t = threadIdx.x;
    float su = 0.f, sv = 0.f;
    for (int n = 0; n < HH; n++) {
        su = fmaf(Wq[(size_t)l*HSQ + (size_t)t*HH + n], bkv[l*HH + n], su);
        sv = fmaf(Wk[(size_t)l*HSQ + (size_t)t*HH + n], bqv[l*HH + n], sv);
    }
    g_u[l*HH + t] = su;
    g_v[l*HH + t] = sv;
    if (t == 0) {
        float c = 0.f;
        for (int n = 0; n < HH; n++) c = fmaf(bqv[l*HH + n], bkv[l*HH + n], c);
        g_c[l] = c;
    }
}

// ---------------- prep: pre-split Wvm, Wvp ----------------
__global__ void k_wsplit2(const float* __restrict__ Wvm, const float* __restrict__ Wvp)
{
    int m = blockIdx.x;        // l*2 + which
    int l = m >> 1;
    const float* W = ((m & 1) ? Wvp : Wvm) + (size_t)l*HSQ;
    float2* O = ((m & 1) ? g_wvp2 : g_wvm2) + (size_t)l*HSQ;
    for (int i = threadIdx.x; i < HSQ; i += blockDim.x) {
        float w = W[i];
        float h = __uint_as_float(__float_as_uint(w) & 0xffffe000u);
        O[i] = make_float2(h, w - h);
    }
}

// ---------------- fused layer kernel: all 4 layers per molecule ----------------
__global__ __launch_bounds__(512) void k_layer(
    const int* __restrict__ ei, const float* __restrict__ ea,
    const float* __restrict__ We, const float* __restrict__ be,
    const float* __restrict__ ds,
    const float* __restrict__ lng, const float* __restrict__ lnb,
    const float* __restrict__ bvm, const float* __restrict__ bvp)
{
    extern __shared__ float sm[];
    float* S1 = sm;                 // mag (persistent)
    float* S2 = sm +   NN*ASTR;     // t / scores / probs
    float* S3 = sm + 2*NN*ASTR;     // bias / U / V
    __shared__ float sru[NN], srv[NN];

    int b = blockIdx.x, tid = threadIdx.x;
    int wid = tid >> 5, lane = tid & 31;
    int gid = lane >> 2, tig = lane & 3;
    int wrm = (wid & 3) * 32, wrn = (wid >> 2) * 32;
    size_t base = (size_t)b*NH;
    float* php = g_ph + base;
    const float scale = 0.08838834764831845f;   // 1/sqrt(128)

    // load mag into S1
#pragma unroll
    for (int it = 0; it < 8; it++) {
        int idx = tid + 512*it;
        int r = idx >> 5, c = (idx & 31) * 4;
        *(float4*)(S1 + r*ASTR + c) = *(const float4*)(g_mag + base + (size_t)r*HH + c);
    }
    __syncthreads();

    float acc[2][4][4];

#pragma unroll 1
    for (int l = 0; l < LL; l++) {
        float cL = __ldg(&g_c[l]);

        // ---- zero S3 + compute ru/rv ----
        for (int i = tid; i < NN*ASTR/4; i += 512) ((float4*)S3)[i] = make_float4(0.f, 0.f, 0.f, 0.f);
        {
            int row = tid >> 2, qtr = tid & 3;
            const float* uu = g_u + l*HH + 32*qtr;
            const float* vv = g_v + l*HH + 32*qtr;
            const float* rowp = S1 + row*ASTR + 32*qtr;
            float pu = 0.f, pv = 0.f;
#pragma unroll
            for (int j = 0; j < 32; j++) {
                float mv = rowp[j];
                pu = fmaf(mv, __ldg(uu + j), pu);
                pv = fmaf(mv, __ldg(vv + j), pv);
            }
            pu += __shfl_xor_sync(0xffffffffu, pu, 1);
            pu += __shfl_xor_sync(0xffffffffu, pu, 2);
            pv += __shfl_xor_sync(0xffffffffu, pv, 1);
            pv += __shfl_xor_sync(0xffffffffu, pv, 2);
            if (qtr == 0) { sru[row] = pu; srv[row] = pv; }
        }
        __syncthreads();

        // ---- edge bias scatter into S3 ----
        {
            float w0 = We[l*4+0], w1 = We[l*4+1], w2 = We[l*4+2], w3 = We[l*4+3];
            float beL = be[l], dsL = ds[l];
            for (int e = tid; e < EE; e += 512) {
                int i0 = ei[(size_t)b*2*EE + e];
                int j0 = ei[(size_t)b*2*EE + EE + e];
                const float* a = ea + ((size_t)b*EE + e)*EDIM;
                float v = fmaf(a[0], w0, fmaf(a[1], w1, fmaf(a[2], w2, fmaf(a[3], w3, beL)))) + dsL*a[0];
                atomicAdd(&S3[i0*ASTR + j0], v);
            }
        }
        __syncthreads();

        // ---- phase 2: t = mag @ M  -> S2 ----
        gemm_core<2>(S1, nullptr, g_m2 + (size_t)l*HSQ, wrm, wrn, gid, tig, acc);
#pragma unroll
        for (int mt = 0; mt < 2; mt++) {
            int r0 = wrm + mt*16 + gid;
#pragma unroll
            for (int nt = 0; nt < 4; nt++) {
                int c = wrn + nt*8 + 2*tig;
                *(float2*)(S2 + r0*ASTR + c)     = make_float2(acc[mt][nt][0], acc[mt][nt][1]);
                *(float2*)(S2 + (r0+8)*ASTR + c) = make_float2(acc[mt][nt][2], acc[mt][nt][3]);
            }
        }
        __syncthreads();

        // ---- phase 3: scores = (t @ mag^T + ru + rv + c)*scale + bias, in-place S2 ----
        gemm_core<0>(S2, S1, nullptr, wrm, wrn, gid, tig, acc);
        __syncthreads();   // all reads of S2/t done before in-place overwrite
#pragma unroll
        for (int mt = 0; mt < 2; mt++) {
            int r0 = wrm + mt*16 + gid, r1 = r0 + 8;
#pragma unroll
            for (int nt = 0; nt < 4; nt++) {
                int c = wrn + nt*8 + 2*tig;
                float rv0 = srv[c], rv1 = srv[c + 1];
                float s00 = fmaf(acc[mt][nt][0] + sru[r0] + rv0 + cL, scale, S3[r0*ASTR + c]);
                float s01 = fmaf(acc[mt][nt][1] + sru[r0] + rv1 + cL, scale, S3[r0*ASTR + c + 1]);
                float s10 = fmaf(acc[mt][nt][2] + sru[r1] + rv0 + cL, scale, S3[r1*ASTR + c]);
                float s11 = fmaf(acc[mt][nt][3] + sru[r1] + rv1 + cL, scale, S3[r1*ASTR + c + 1]);
                *(float2*)(S2 + r0*ASTR + c) = make_float2(s00, s01);
                *(float2*)(S2 + r1*ASTR + c) = make_float2(s10, s11);
            }
        }
        __syncthreads();

        // ---- phase 4: softmax rows of S2 (4 threads/row) ----
        {
            int row = tid >> 2, qtr = tid & 3;
            float* rp = S2 + row*ASTR + 32*qtr;
            float m = -1e30f;
#pragma unroll
            for (int j = 0; j < 8; j++) {
                float4 v = *(const float4*)(rp + 4*j);
                m = fmaxf(m, fmaxf(fmaxf(v.x, v.y), fmaxf(v.z, v.w)));
            }
            m = fmaxf(m, __shfl_xor_sync(0xffffffffu, m, 1));
            m = fmaxf(m, __shfl_xor_sync(0xffffffffu, m, 2));
            float s = 0.f;
#pragma unroll
            for (int j = 0; j < 8; j++) {
                float4 v = *(float4*)(rp + 4*j);
                v.x = __expf(v.x - m); v.y = __expf(v.y - m);
                v.z = __expf(v.z - m); v.w = __expf(v.w - m);
                s += v.x + v.y + v.z + v.w;
                *(float4*)(rp + 4*j) = v;
            }
            s += __shfl_xor_sync(0xffffffffu, s, 1);
            s += __shfl_xor_sync(0xffffffffu, s, 2);
            float inv = 1.f / s;
#pragma unroll
            for (int j = 0; j < 8; j++) {
                float4 v = *(float4*)(rp + 4*j);
                v.x *= inv; v.y *= inv; v.z *= inv; v.w *= inv;
                *(float4*)(rp + 4*j) = v;
            }
        }
        __syncthreads();

        // ---- phase 5: U = P @ mag -> S3 ----
        gemm_core<1>(S2, S1, nullptr, wrm, wrn, gid, tig, acc);
#pragma unroll
        for (int mt = 0; mt < 2; mt++) {
            int r0 = wrm + mt*16 + gid;
#pragma unroll
            for (int nt = 0; nt < 4; nt++) {
                int c = wrn + nt*8 + 2*tig;
                *(float2*)(S3 + r0*ASTR + c)     = make_float2(acc[mt][nt][0], acc[mt][nt][1]);
                *(float2*)(S3 + (r0+8)*ASTR + c) = make_float2(acc[mt][nt][2], acc[mt][nt][3]);
            }
        }
        __syncthreads();

        // ---- phase 6: new_mag = U @ Wvm + bvm + mag -> S1 (in-place own tile) ----
        gemm_core<2>(S3, nullptr, g_wvm2 + (size_t)l*HSQ, wrm, wrn, gid, tig, acc);
#pragma unroll
        for (int mt = 0; mt < 2; mt++) {
            int r0 = wrm + mt*16 + gid, r1 = r0 + 8;
#pragma unroll
            for (int nt = 0; nt < 4; nt++) {
                int c = wrn + nt*8 + 2*tig;
                float bv0 = __ldg(bvm + l*HH + c), bv1 = __ldg(bvm + l*HH + c + 1);
                float2 o0 = *(float2*)(S1 + r0*ASTR + c);
                float2 o1 = *(float2*)(S1 + r1*ASTR + c);
                o0.x += acc[mt][nt][0] + bv0; o0.y += acc[mt][nt][1] + bv1;
                o1.x += acc[mt][nt][2] + bv0; o1.y += acc[mt][nt][3] + bv1;
                *(float2*)(S1 + r0*ASTR + c) = o0;
                *(float2*)(S1 + r1*ASTR + c) = o1;
            }
        }
        __syncthreads();

        // ---- LayerNorm rows of S1 (4 threads/row) ----
        {
            int row = tid >> 2, qtr = tid & 3;
            float* rp = S1 + row*ASTR + 32*qtr;
            float su = 0.f;
#pragma unroll
            for (int j = 0; j < 8; j++) {
                float4 v = *(const float4*)(rp + 4*j);
                su += v.x + v.y + v.z + v.w;
            }
            su += __shfl_xor_sync(0xffffffffu, su, 1);
            su += __shfl_xor_sync(0xffffffffu, su, 2);
            float mu = su * (1.f/128.f);
            float var = 0.f;
#pragma unroll
            for (int j = 0; j < 8; j++) {
                float4 v = *(const float4*)(rp + 4*j);
                float d0 = v.x - mu, d1 = v.y - mu, d2 = v.z - mu, d3 = v.w - mu;
                var = fmaf(d0, d0, var); var = fmaf(d1, d1, var);
                var = fmaf(d2, d2, var); var = fmaf(d3, d3, var);
            }
            var += __shfl_xor_sync(0xffffffffu, var, 1);
            var += __shfl_xor_sync(0xffffffffu, var, 2);
            float rs = rsqrtf(var * (1.f/128.f) + 1e-5f);
            const float* gp  = lng + l*HH + 32*qtr;
            const float* bp2 = lnb + l*HH + 32*qtr;
#pragma unroll
            for (int j = 0; j < 8; j++) {
                float4 v = *(float4*)(rp + 4*j);
                float4 g = *(const float4*)(gp + 4*j);
                float4 be2 = *(const float4*)(bp2 + 4*j);
                v.x = fmaf(g.x, (v.x - mu)*rs, be2.x);
                v.y = fmaf(g.y, (v.y - mu)*rs, be2.y);
                v.z = fmaf(g.z, (v.z - mu)*rs, be2.z);
                v.w = fmaf(g.w, (v.w - mu)*rs, be2.w);
                *(float4*)(rp + 4*j) = v;
            }
        }
        __syncthreads();

        // ---- phase 7: V = P @ ph(gmem) -> S3 ----
        gemm_core<3>(S2, php, nullptr, wrm, wrn, gid, tig, acc);
#pragma unroll
        for (int mt = 0; mt < 2; mt++) {
            int r0 = wrm + mt*16 + gid;
#pragma unroll
            for (int nt = 0; nt < 4; nt++) {
                int c = wrn + nt*8 + 2*tig;
                *(float2*)(S3 + r0*ASTR + c)     = make_float2(acc[mt][nt][0], acc[mt][nt][1]);
                *(float2*)(S3 + (r0+8)*ASTR + c) = make_float2(acc[mt][nt][2], acc[mt][nt][3]);
            }
        }
        __syncthreads();

        // ---- phase 8: new_ph = V @ Wvp + bvp + ph -> gmem ph ----
        gemm_core<2>(S3, nullptr, g_wvp2 + (size_t)l*HSQ, wrm, wrn, gid, tig, acc);
#pragma unroll
        for (int mt = 0; mt < 2; mt++) {
            int r0 = wrm + mt*16 + gid, r1 = r0 + 8;
#pragma unroll
            for (int nt = 0; nt < 4; nt++) {
                int c = wrn + nt*8 + 2*tig;
                float bv0 = __ldg(bvp + l*HH + c), bv1 = __ldg(bvp + l*HH + c + 1);
                float2 o0 = *(float2*)(php + (size_t)r0*HH + c);
                float2 o1 = *(float2*)(php + (size_t)r1*HH + c);
                o0.x += acc[mt][nt][0] + bv0; o0.y += acc[mt][nt][1] + bv1;
                o1.x += acc[mt][nt][2] + bv0; o1.y += acc[mt][nt][3] + bv1;
                *(float2*)(php + (size_t)r0*HH + c) = o0;
                *(float2*)(php + (size_t)r1*HH + c) = o1;
            }
        }
        __syncthreads();
    }

    // write final mag back
#pragma unroll
    for (int it = 0; it < 8; it++) {
        int idx = tid + 512*it;
        int r = idx >> 5, c = (idx & 31) * 4;
        *(float4*)(g_mag + base + (size_t)r*HH + c) = *(const float4*)(S1 + r*ASTR + c);
    }
}

// ---------------- K3: head ----------------
__global__ void k_head(const float* __restrict__ rpW, const float* __restrict__ rpb,
                       const float* __restrict__ h1W, const float* __restrict__ h1b,
                       const float* __restrict__ h2W, const float* __restrict__ h2b,
                       float* __restrict__ out)
{
    int b = blockIdx.x, t = threadIdx.x;
    __shared__ float sS[2*HH];
    __shared__ float sp[2*HH];
    __shared__ float sr[HH];
    size_t base = (size_t)b*NH;

    float ac = 0.f, as = 0.f;
    for (int n = 0; n < NN; n++) {
        float m = g_mag[base + (size_t)n*HH + t];
        float p = g_ph [base + (size_t)n*HH + t];
        float si, co;
        sincosf(p, &si, &co);
        ac = fmaf(m, co, ac);
        as = fmaf(m, si, as);
    }
    sS[t] = ac; sS[HH + t] = as;
    __syncthreads();

    float d = 0.f;
    for (int c = 0; c < 2*HH; c++) d = fmaf(sS[c], rpW[(size_t)c*HH + t], d);
    float sumr = d + 128.f * rpb[t];
    sp[t]      = sumr * (1.f/128.f);
    sp[HH + t] = sumr;
    __syncthreads();

    float hv = h1b[t];
    for (int c = 0; c < 2*HH; c++) hv = fmaf(sp[c], h1W[(size_t)c*HH + t], hv);
    hv = hv / (1.f + expf(-hv));
    sr[t] = hv * h2W[t];
    __syncthreads();

    for (int s = 64; s >= 1; s >>= 1) {
        if (t < s) sr[t] += sr[t + s];
        __syncthreads();
    }
    if (t == 0) out[b] = sr[0] + h2b[0];
}

// ---------------- launch ----------------
extern "C" void kernel_launch(void* const* d_in, const int* in_sizes, int n_in,
                              void* d_out, int out_size)
{
    const float* at   = (const float*)d_in[0];
    const float* sph  = (const float*)d_in[1];
    const int*   ei   = (const int*)  d_in[2];
    const float* ea   = (const float*)d_in[3];
    const float* Wm   = (const float*)d_in[4];
    const float* bm   = (const float*)d_in[5];
    const float* Wp   = (const float*)d_in[6];
    const float* bp   = (const float*)d_in[7];
    const float* Wq   = (const float*)d_in[8];
    const float* bq   = (const float*)d_in[9];
    const float* Wk   = (const float*)d_in[10];
    const float* bk   = (const float*)d_in[11];
    const float* Wvm  = (const float*)d_in[12];
    const float* bvm  = (const float*)d_in[13];
    const float* Wvp  = (const float*)d_in[14];
    const float* bvp  = (const float*)d_in[15];
    const float* We   = (const float*)d_in[16];
    const float* be   = (const float*)d_in[17];
    const float* ds   = (const float*)d_in[18];
    const float* lng  = (const float*)d_in[19];
    const float* lnb  = (const float*)d_in[20];
    const float* rpW  = (const float*)d_in[21];
    const float* rpb  = (const float*)d_in[22];
    const float* h1W  = (const float*)d_in[23];
    const float* h1b  = (const float*)d_in[24];
    const float* h2W  = (const float*)d_in[25];
    const float* h2b  = (const float*)d_in[26];
    float* out = (float*)d_out;

    size_t layer_smem = (size_t)3 * NN * ASTR * sizeof(float);   // 202752
    cudaFuncSetAttribute(k_layer, cudaFuncAttributeMaxDynamicSharedMemorySize, (int)layer_smem);

    k_embed<<<BB, 128>>>(at, sph, Wm, bm, Wp, bp);
    k_prep_m<<<dim3(LL, 4, 4), 256>>>(Wq, Wk);
    k_prep_uv<<<LL, 128>>>(Wq, Wk, bq, bk);
    k_wsplit2<<<2*LL, 256>>>(Wvm, Wvp);

    k_layer<<<BB, 512, layer_smem>>>(ei, ea, We, be, ds, lng, lnb, bvm, bvp);

    k_head<<<BB, 128>>>(rpW, rpb, h1W, h1b, h2W, h2b, out);
}

// round 10
// speedup vs baseline: 2.3262x; 1.0221x over previous
#include <cuda_runtime.h>
#include <math.h>
#include <stdint.h>

#define BB   1024
#define NN   128
#define EE   1024
#define HH   128
#define LL   4
#define INDIM 16
#define DIN  19
#define EDIM 4
#define NH   (NN*HH)      // 16384
#define HSQ  (HH*HH)      // 16384
#define ASTR 132

// ---------------- device scratch ----------------
__device__ float  g_mag[(size_t)BB*NH];
__device__ float  g_ph [(size_t)BB*NH];
__device__ float2 g_m2  [(size_t)LL*HSQ];   // pre-split Wq@Wk^T
__device__ float2 g_wvm2[(size_t)LL*HSQ];   // pre-split Wvm
__device__ float2 g_wvp2[(size_t)LL*HSQ];   // pre-split Wvp
__device__ float  g_u[LL*HH];
__device__ float  g_v[LL*HH];
__device__ float  g_c[LL];

// ---------------- helpers ----------------
__device__ __forceinline__ void splitT(float x, uint32_t& hi, uint32_t& lo) {
    uint32_t h = __float_as_uint(x) & 0xffffe000u;
    hi = h;
    lo = __float_as_uint(x - __uint_as_float(h));
}
__device__ __forceinline__ void mma8(float* c, const uint32_t* a, uint32_t b0, uint32_t b1) {
    asm volatile("mma.sync.aligned.m16n8k8.row.col.f32.tf32.tf32.f32 "
        "{%0,%1,%2,%3}, {%4,%5,%6,%7}, {%8,%9}, {%0,%1,%2,%3};"
        : "+f"(c[0]), "+f"(c[1]), "+f"(c[2]), "+f"(c[3])
        : "r"(a[0]), "r"(a[1]), "r"(a[2]), "r"(a[3]), "r"(b0), "r"(b1));
}
__device__ __forceinline__ void mma3x(float* c0, float* c1,
                                      const uint32_t* ah0, const uint32_t* al0,
                                      const uint32_t* ah1, const uint32_t* al1,
                                      uint32_t bh0, uint32_t bh1, uint32_t bl0, uint32_t bl1) {
    mma8(c0, ah0, bh0, bh1);
    mma8(c1, ah1, bh0, bh1);
    mma8(c0, ah0, bl0, bl1);
    mma8(c1, ah1, bl0, bl1);
    mma8(c0, al0, bh0, bh1);
    mma8(c1, al1, bh0, bh1);
}

// GEMM core: A from smem (stride ASTR) with in-loop split; B by kind:
//   BK=0: smem B^T pattern (B[k][n] = Bf[n][k]), stride ASTR
//   BK=1: smem B  pattern (B[k][n] = Bf[k][n]), stride ASTR
//   BK=2: gmem pre-split float2 [k][n], stride 128
template<int BK>
__device__ __forceinline__ void gemm_core(const float* SA_, const float* Bf, const float2* B2,
                                          int wrm, int wrn, int gid, int tig,
                                          float acc[2][4][4])
{
#pragma unroll
    for (int i = 0; i < 2; i++)
#pragma unroll
        for (int j = 0; j < 4; j++)
#pragma unroll
            for (int q = 0; q < 4; q++) acc[i][j][q] = 0.f;
#pragma unroll
    for (int k0 = 0; k0 < 128; k0 += 8) {
        uint32_t ah[2][4], al[2][4];
#pragma unroll
        for (int mt = 0; mt < 2; mt++) {
            int rb = wrm + mt*16;
            splitT(SA_[(rb + gid    )*ASTR + k0 + tig    ], ah[mt][0], al[mt][0]);
            splitT(SA_[(rb + gid + 8)*ASTR + k0 + tig    ], ah[mt][1], al[mt][1]);
            splitT(SA_[(rb + gid    )*ASTR + k0 + tig + 4], ah[mt][2], al[mt][2]);
            splitT(SA_[(rb + gid + 8)*ASTR + k0 + tig + 4], ah[mt][3], al[mt][3]);
        }
#pragma unroll
        for (int nt = 0; nt < 4; nt++) {
            int nb = wrn + nt*8;
            uint32_t bh0, bl0, bh1, bl1;
            if (BK == 0) {
                splitT(Bf[(nb + gid)*ASTR + k0 + tig    ], bh0, bl0);
                splitT(Bf[(nb + gid)*ASTR + k0 + tig + 4], bh1, bl1);
            } else if (BK == 1) {
                splitT(Bf[(k0 + tig    )*ASTR + nb + gid], bh0, bl0);
                splitT(Bf[(k0 + tig + 4)*ASTR + nb + gid], bh1, bl1);
            } else {
                float2 b0 = __ldg(&B2[(k0 + tig    )*128 + nb + gid]);
                float2 b1 = __ldg(&B2[(k0 + tig + 4)*128 + nb + gid]);
                bh0 = __float_as_uint(b0.x); bl0 = __float_as_uint(b0.y);
                bh1 = __float_as_uint(b1.x); bl1 = __float_as_uint(b1.y);
            }
            mma3x(acc[0][nt], acc[1][nt], ah[0], al[0], ah[1], al[1], bh0, bh1, bl0, bl1);
        }
    }
}

// Dual-B GEMM: A from smem (split once), B1 = smem pattern [k][n] (mag),
// B2 = gmem fp32 [k][n] stride 128 (ph). Two accumulator sets.
__device__ __forceinline__ void gemm_dual(const float* SA_, const float* B1f, const float* B2f,
                                          int wrm, int wrn, int gid, int tig,
                                          float accU[2][4][4], float accV[2][4][4])
{
#pragma unroll
    for (int i = 0; i < 2; i++)
#pragma unroll
        for (int j = 0; j < 4; j++)
#pragma unroll
            for (int q = 0; q < 4; q++) { accU[i][j][q] = 0.f; accV[i][j][q] = 0.f; }
#pragma unroll
    for (int k0 = 0; k0 < 128; k0 += 8) {
        uint32_t ah[2][4], al[2][4];
#pragma unroll
        for (int mt = 0; mt < 2; mt++) {
            int rb = wrm + mt*16;
            splitT(SA_[(rb + gid    )*ASTR + k0 + tig    ], ah[mt][0], al[mt][0]);
            splitT(SA_[(rb + gid + 8)*ASTR + k0 + tig    ], ah[mt][1], al[mt][1]);
            splitT(SA_[(rb + gid    )*ASTR + k0 + tig + 4], ah[mt][2], al[mt][2]);
            splitT(SA_[(rb + gid + 8)*ASTR + k0 + tig + 4], ah[mt][3], al[mt][3]);
        }
#pragma unroll
        for (int nt = 0; nt < 4; nt++) {
            int nb = wrn + nt*8;
            uint32_t bh0, bl0, bh1, bl1;
            splitT(B1f[(k0 + tig    )*ASTR + nb + gid], bh0, bl0);
            splitT(B1f[(k0 + tig + 4)*ASTR + nb + gid], bh1, bl1);
            mma3x(accU[0][nt], accU[1][nt], ah[0], al[0], ah[1], al[1], bh0, bh1, bl0, bl1);
            splitT(__ldg(&B2f[(k0 + tig    )*128 + nb + gid]), bh0, bl0);
            splitT(__ldg(&B2f[(k0 + tig + 4)*128 + nb + gid]), bh1, bl1);
            mma3x(accV[0][nt], accV[1][nt], ah[0], al[0], ah[1], al[1], bh0, bh1, bl0, bl1);
        }
    }
}

// ---------------- K0: complex embedding ----------------
__global__ void k_embed(const float* __restrict__ at, const float* __restrict__ sph,
                        const float* __restrict__ Wm, const float* __restrict__ bm,
                        const float* __restrict__ Wp, const float* __restrict__ bp)
{
    int b = blockIdx.x, t = threadIdx.x;
    __shared__ float sx[NN][20];
    for (int i = t; i < NN*DIN; i += blockDim.x) {
        int n = i / DIN, d = i % DIN;
        sx[n][d] = (d < INDIM) ? at[((size_t)b*NN + n)*INDIM + d]
                               : sph[((size_t)b*NN + n)*3 + (d - INDIM)];
    }
    __syncthreads();
    float wm[DIN], wp[DIN];
#pragma unroll
    for (int d = 0; d < DIN; d++) { wm[d] = Wm[d*HH + t]; wp[d] = Wp[d*HH + t]; }
    float bmv = bm[t], bpv = bp[t];
    size_t base = (size_t)b*NH;
    for (int n = 0; n < NN; n++) {
        float am = bmv, ap = bpv;
#pragma unroll
        for (int d = 0; d < DIN; d++) { float x = sx[n][d]; am = fmaf(x, wm[d], am); ap = fmaf(x, wp[d], ap); }
        g_mag[base + (size_t)n*HH + t] = am;
        g_ph [base + (size_t)n*HH + t] = ap;
    }
}

// ---------------- prep: M = Wq@Wk^T (pre-split) ----------------
__global__ void k_prep_m(const float* __restrict__ Wq, const float* __restrict__ Wk)
{
    __shared__ float sq[32][129], sk[32][129];
    int l = blockIdx.x, bi = blockIdx.y, bj = blockIdx.z;
    const float* q = Wq + (size_t)l*HSQ + bi*32*HH;
    const float* k = Wk + (size_t)l*HSQ + bj*32*HH;
    int tid = threadIdx.x;
    for (int i = tid; i < 32*128; i += 256) {
        sq[i >> 7][i & 127] = q[(i >> 7)*HH + (i & 127)];
        sk[i >> 7][i & 127] = k[(i >> 7)*HH + (i & 127)];
    }
    __syncthreads();
    int i = tid >> 3, j0 = (tid & 7) * 4;
    for (int jj = 0; jj < 4; jj++) {
        int j = j0 + jj;
        float s = 0.f;
        for (int n = 0; n < 128; n++) s = fmaf(sq[i][n], sk[j][n], s);
        float h = __uint_as_float(__float_as_uint(s) & 0xffffe000u);
        g_m2[(size_t)l*HSQ + (size_t)(bi*32 + i)*HH + bj*32 + j] = make_float2(h, s - h);
    }
}

// ---------------- prep: u = Wq@bk, v = Wk@bq, c = bq.bk ----------------
__global__ void k_prep_uv(const float* __restrict__ Wq, const float* __restrict__ Wk,
                          const float* __restrict__ bqv, const float* __restrict__ bkv)
{
    int l = blockIdx.x, t = threadIdx.x;
    float su = 0.f, sv = 0.f;
    for (int n = 0; n < HH; n++) {
        su = fmaf(Wq[(size_t)l*HSQ + (size_t)t*HH + n], bkv[l*HH + n], su);
        sv = fmaf(Wk[(size_t)l*HSQ + (size_t)t*HH + n], bqv[l*HH + n], sv);
    }
    g_u[l*HH + t] = su;
    g_v[l*HH + t] = sv;
    if (t == 0) {
        float c = 0.f;
        for (int n = 0; n < HH; n++) c = fmaf(bqv[l*HH + n], bkv[l*HH + n], c);
        g_c[l] = c;
    }
}

// ---------------- prep: pre-split Wvm, Wvp ----------------
__global__ void k_wsplit2(const float* __restrict__ Wvm, const float* __restrict__ Wvp)
{
    int m = blockIdx.x;        // l*2 + which
    int l = m >> 1;
    const float* W = ((m & 1) ? Wvp : Wvm) + (size_t)l*HSQ;
    float2* O = ((m & 1) ? g_wvp2 : g_wvm2) + (size_t)l*HSQ;
    for (int i = threadIdx.x; i < HSQ; i += blockDim.x) {
        float w = W[i];
        float h = __uint_as_float(__float_as_uint(w) & 0xffffe000u);
        O[i] = make_float2(h, w - h);
    }
}

// ---------------- fused layer kernel: all 4 layers per molecule ----------------
__global__ __launch_bounds__(512) void k_layer(
    const int* __restrict__ ei, const float* __restrict__ ea,
    const float* __restrict__ We, const float* __restrict__ be,
    const float* __restrict__ ds,
    const float* __restrict__ lng, const float* __restrict__ lnb,
    const float* __restrict__ bvm, const float* __restrict__ bvp)
{
    extern __shared__ float sm[];
    float* S1 = sm;                 // mag (persistent)
    float* S2 = sm +   NN*ASTR;     // t / scores / probs / V
    float* S3 = sm + 2*NN*ASTR;     // bias / U
    __shared__ float sru[NN], srv[NN];

    int b = blockIdx.x, tid = threadIdx.x;
    int wid = tid >> 5, lane = tid & 31;
    int gid = lane >> 2, tig = lane & 3;
    int wrm = (wid & 3) * 32, wrn = (wid >> 2) * 32;
    size_t base = (size_t)b*NH;
    float* php = g_ph + base;
    const float scale = 0.08838834764831845f;   // 1/sqrt(128)

    // load mag into S1
#pragma unroll
    for (int it = 0; it < 8; it++) {
        int idx = tid + 512*it;
        int r = idx >> 5, c = (idx & 31) * 4;
        *(float4*)(S1 + r*ASTR + c) = *(const float4*)(g_mag + base + (size_t)r*HH + c);
    }
    __syncthreads();

    float acc[2][4][4];
    float accV[2][4][4];

#pragma unroll 1
    for (int l = 0; l < LL; l++) {
        float cL = __ldg(&g_c[l]);

        // ---- zero S3 + compute ru/rv ----
        for (int i = tid; i < NN*ASTR/4; i += 512) ((float4*)S3)[i] = make_float4(0.f, 0.f, 0.f, 0.f);
        {
            int row = tid >> 2, qtr = tid & 3;
            const float* uu = g_u + l*HH + 32*qtr;
            const float* vv = g_v + l*HH + 32*qtr;
            const float* rowp = S1 + row*ASTR + 32*qtr;
            float pu = 0.f, pv = 0.f;
#pragma unroll
            for (int j = 0; j < 32; j++) {
                float mv = rowp[j];
                pu = fmaf(mv, __ldg(uu + j), pu);
                pv = fmaf(mv, __ldg(vv + j), pv);
            }
            pu += __shfl_xor_sync(0xffffffffu, pu, 1);
            pu += __shfl_xor_sync(0xffffffffu, pu, 2);
            pv += __shfl_xor_sync(0xffffffffu, pv, 1);
            pv += __shfl_xor_sync(0xffffffffu, pv, 2);
            if (qtr == 0) { sru[row] = pu; srv[row] = pv; }
        }
        __syncthreads();

        // ---- edge bias scatter into S3 ----
        {
            float w0 = We[l*4+0], w1 = We[l*4+1], w2 = We[l*4+2], w3 = We[l*4+3];
            float beL = be[l], dsL = ds[l];
            for (int e = tid; e < EE; e += 512) {
                int i0 = ei[(size_t)b*2*EE + e];
                int j0 = ei[(size_t)b*2*EE + EE + e];
                const float* a = ea + ((size_t)b*EE + e)*EDIM;
                float v = fmaf(a[0], w0, fmaf(a[1], w1, fmaf(a[2], w2, fmaf(a[3], w3, beL)))) + dsL*a[0];
                atomicAdd(&S3[i0*ASTR + j0], v);
            }
        }
        __syncthreads();

        // ---- phase 2: t = mag @ M  -> S2 ----
        gemm_core<2>(S1, nullptr, g_m2 + (size_t)l*HSQ, wrm, wrn, gid, tig, acc);
#pragma unroll
        for (int mt = 0; mt < 2; mt++) {
            int r0 = wrm + mt*16 + gid;
#pragma unroll
            for (int nt = 0; nt < 4; nt++) {
                int c = wrn + nt*8 + 2*tig;
                *(float2*)(S2 + r0*ASTR + c)     = make_float2(acc[mt][nt][0], acc[mt][nt][1]);
                *(float2*)(S2 + (r0+8)*ASTR + c) = make_float2(acc[mt][nt][2], acc[mt][nt][3]);
            }
        }
        __syncthreads();

        // ---- phase 3: scores = (t @ mag^T + ru + rv + c)*scale + bias, in-place S2 ----
        gemm_core<0>(S2, S1, nullptr, wrm, wrn, gid, tig, acc);
        __syncthreads();   // all reads of S2/t done before in-place overwrite
#pragma unroll
        for (int mt = 0; mt < 2; mt++) {
            int r0 = wrm + mt*16 + gid, r1 = r0 + 8;
#pragma unroll
            for (int nt = 0; nt < 4; nt++) {
                int c = wrn + nt*8 + 2*tig;
                float rv0 = srv[c], rv1 = srv[c + 1];
                float s00 = fmaf(acc[mt][nt][0] + sru[r0] + rv0 + cL, scale, S3[r0*ASTR + c]);
                float s01 = fmaf(acc[mt][nt][1] + sru[r0] + rv1 + cL, scale, S3[r0*ASTR + c + 1]);
                float s10 = fmaf(acc[mt][nt][2] + sru[r1] + rv0 + cL, scale, S3[r1*ASTR + c]);
                float s11 = fmaf(acc[mt][nt][3] + sru[r1] + rv1 + cL, scale, S3[r1*ASTR + c + 1]);
                *(float2*)(S2 + r0*ASTR + c) = make_float2(s00, s01);
                *(float2*)(S2 + r1*ASTR + c) = make_float2(s10, s11);
            }
        }
        __syncthreads();

        // ---- phase 4: softmax rows of S2 (4 threads/row) ----
        {
            int row = tid >> 2, qtr = tid & 3;
            float* rp = S2 + row*ASTR + 32*qtr;
            float m = -1e30f;
#pragma unroll
            for (int j = 0; j < 8; j++) {
                float4 v = *(const float4*)(rp + 4*j);
                m = fmaxf(m, fmaxf(fmaxf(v.x, v.y), fmaxf(v.z, v.w)));
            }
            m = fmaxf(m, __shfl_xor_sync(0xffffffffu, m, 1));
            m = fmaxf(m, __shfl_xor_sync(0xffffffffu, m, 2));
            float s = 0.f;
#pragma unroll
            for (int j = 0; j < 8; j++) {
                float4 v = *(float4*)(rp + 4*j);
                v.x = __expf(v.x - m); v.y = __expf(v.y - m);
                v.z = __expf(v.z - m); v.w = __expf(v.w - m);
                s += v.x + v.y + v.z + v.w;
                *(float4*)(rp + 4*j) = v;
            }
            s += __shfl_xor_sync(0xffffffffu, s, 1);
            s += __shfl_xor_sync(0xffffffffu, s, 2);
            float inv = 1.f / s;
#pragma unroll
            for (int j = 0; j < 8; j++) {
                float4 v = *(float4*)(rp + 4*j);
                v.x *= inv; v.y *= inv; v.z *= inv; v.w *= inv;
                *(float4*)(rp + 4*j) = v;
            }
        }
        __syncthreads();

        // ---- phase 5+7 merged: U = P @ mag, V = P @ ph (shared A loads/splits) ----
        gemm_dual(S2, S1, php, wrm, wrn, gid, tig, acc, accV);
        // U -> S3 (free)
#pragma unroll
        for (int mt = 0; mt < 2; mt++) {
            int r0 = wrm + mt*16 + gid;
#pragma unroll
            for (int nt = 0; nt < 4; nt++) {
                int c = wrn + nt*8 + 2*tig;
                *(float2*)(S3 + r0*ASTR + c)     = make_float2(acc[mt][nt][0], acc[mt][nt][1]);
                *(float2*)(S3 + (r0+8)*ASTR + c) = make_float2(acc[mt][nt][2], acc[mt][nt][3]);
            }
        }
        __syncthreads();   // all reads of P (S2) complete
        // V -> S2 (overwrites P)
#pragma unroll
        for (int mt = 0; mt < 2; mt++) {
            int r0 = wrm + mt*16 + gid;
#pragma unroll
            for (int nt = 0; nt < 4; nt++) {
                int c = wrn + nt*8 + 2*tig;
                *(float2*)(S2 + r0*ASTR + c)     = make_float2(accV[mt][nt][0], accV[mt][nt][1]);
                *(float2*)(S2 + (r0+8)*ASTR + c) = make_float2(accV[mt][nt][2], accV[mt][nt][3]);
            }
        }
        __syncthreads();

        // ---- phase 6: new_mag = U @ Wvm + bvm + mag -> S1 (in-place own tile) ----
        gemm_core<2>(S3, nullptr, g_wvm2 + (size_t)l*HSQ, wrm, wrn, gid, tig, acc);
#pragma unroll
        for (int mt = 0; mt < 2; mt++) {
            int r0 = wrm + mt*16 + gid, r1 = r0 + 8;
#pragma unroll
            for (int nt = 0; nt < 4; nt++) {
                int c = wrn + nt*8 + 2*tig;
                float bv0 = __ldg(bvm + l*HH + c), bv1 = __ldg(bvm + l*HH + c + 1);
                float2 o0 = *(float2*)(S1 + r0*ASTR + c);
                float2 o1 = *(float2*)(S1 + r1*ASTR + c);
                o0.x += acc[mt][nt][0] + bv0; o0.y += acc[mt][nt][1] + bv1;
                o1.x += acc[mt][nt][2] + bv0; o1.y += acc[mt][nt][3] + bv1;
                *(float2*)(S1 + r0*ASTR + c) = o0;
                *(float2*)(S1 + r1*ASTR + c) = o1;
            }
        }
        __syncthreads();

        // ---- LayerNorm rows of S1 (4 threads/row) ----
        {
            int row = tid >> 2, qtr = tid & 3;
            float* rp = S1 + row*ASTR + 32*qtr;
            float su = 0.f;
#pragma unroll
            for (int j = 0; j < 8; j++) {
                float4 v = *(const float4*)(rp + 4*j);
                su += v.x + v.y + v.z + v.w;
            }
            su += __shfl_xor_sync(0xffffffffu, su, 1);
            su += __shfl_xor_sync(0xffffffffu, su, 2);
            float mu = su * (1.f/128.f);
            float var = 0.f;
#pragma unroll
            for (int j = 0; j < 8; j++) {
                float4 v = *(const float4*)(rp + 4*j);
                float d0 = v.x - mu, d1 = v.y - mu, d2 = v.z - mu, d3 = v.w - mu;
                var = fmaf(d0, d0, var); var = fmaf(d1, d1, var);
                var = fmaf(d2, d2, var); var = fmaf(d3, d3, var);
            }
            var += __shfl_xor_sync(0xffffffffu, var, 1);
            var += __shfl_xor_sync(0xffffffffu, var, 2);
            float rs = rsqrtf(var * (1.f/128.f) + 1e-5f);
            const float* gp  = lng + l*HH + 32*qtr;
            const float* bp2 = lnb + l*HH + 32*qtr;
#pragma unroll
            for (int j = 0; j < 8; j++) {
                float4 v = *(float4*)(rp + 4*j);
                float4 g = *(const float4*)(gp + 4*j);
                float4 be2 = *(const float4*)(bp2 + 4*j);
                v.x = fmaf(g.x, (v.x - mu)*rs, be2.x);
                v.y = fmaf(g.y, (v.y - mu)*rs, be2.y);
                v.z = fmaf(g.z, (v.z - mu)*rs, be2.z);
                v.w = fmaf(g.w, (v.w - mu)*rs, be2.w);
                *(float4*)(rp + 4*j) = v;
            }
        }
        __syncthreads();

        // ---- phase 8: new_ph = V @ Wvp + bvp + ph -> gmem ph ----
        gemm_core<2>(S2, nullptr, g_wvp2 + (size_t)l*HSQ, wrm, wrn, gid, tig, acc);
#pragma unroll
        for (int mt = 0; mt < 2; mt++) {
            int r0 = wrm + mt*16 + gid, r1 = r0 + 8;
#pragma unroll
            for (int nt = 0; nt < 4; nt++) {
                int c = wrn + nt*8 + 2*tig;
                float bv0 = __ldg(bvp + l*HH + c), bv1 = __ldg(bvp + l*HH + c + 1);
                float2 o0 = *(float2*)(php + (size_t)r0*HH + c);
                float2 o1 = *(float2*)(php + (size_t)r1*HH + c);
                o0.x += acc[mt][nt][0] + bv0; o0.y += acc[mt][nt][1] + bv1;
                o1.x += acc[mt][nt][2] + bv0; o1.y += acc[mt][nt][3] + bv1;
                *(float2*)(php + (size_t)r0*HH + c) = o0;
                *(float2*)(php + (size_t)r1*HH + c) = o1;
            }
        }
        __syncthreads();
    }

    // write final mag back
#pragma unroll
    for (int it = 0; it < 8; it++) {
        int idx = tid + 512*it;
        int r = idx >> 5, c = (idx & 31) * 4;
        *(float4*)(g_mag + base + (size_t)r*HH + c) = *(const float4*)(S1 + r*ASTR + c);
    }
}

// ---------------- K3: head ----------------
__global__ void k_head(const float* __restrict__ rpW, const float* __restrict__ rpb,
                       const float* __restrict__ h1W, const float* __restrict__ h1b,
                       const float* __restrict__ h2W, const float* __restrict__ h2b,
                       float* __restrict__ out)
{
    int b = blockIdx.x, t = threadIdx.x;
    __shared__ float sS[2*HH];
    __shared__ float sp[2*HH];
    __shared__ float sr[HH];
    size_t base = (size_t)b*NH;

    float ac = 0.f, as = 0.f;
    for (int n = 0; n < NN; n++) {
        float m = g_mag[base + (size_t)n*HH + t];
        float p = g_ph [base + (size_t)n*HH + t];
        float si, co;
        sincosf(p, &si, &co);
        ac = fmaf(m, co, ac);
        as = fmaf(m, si, as);
    }
    sS[t] = ac; sS[HH + t] = as;
    __syncthreads();

    float d = 0.f;
    for (int c = 0; c < 2*HH; c++) d = fmaf(sS[c], rpW[(size_t)c*HH + t], d);
    float sumr = d + 128.f * rpb[t];
    sp[t]      = sumr * (1.f/128.f);
    sp[HH + t] = sumr;
    __syncthreads();

    float hv = h1b[t];
    for (int c = 0; c < 2*HH; c++) hv = fmaf(sp[c], h1W[(size_t)c*HH + t], hv);
    hv = hv / (1.f + expf(-hv));
    sr[t] = hv * h2W[t];
    __syncthreads();

    for (int s = 64; s >= 1; s >>= 1) {
        if (t < s) sr[t] += sr[t + s];
        __syncthreads();
    }
    if (t == 0) out[b] = sr[0] + h2b[0];
}

// ---------------- launch ----------------
extern "C" void kernel_launch(void* const* d_in, const int* in_sizes, int n_in,
                              void* d_out, int out_size)
{
    const float* at   = (const float*)d_in[0];
    const float* sph  = (const float*)d_in[1];
    const int*   ei   = (const int*)  d_in[2];
    const float* ea   = (const float*)d_in[3];
    const float* Wm   = (const float*)d_in[4];
    const float* bm   = (const float*)d_in[5];
    const float* Wp   = (const float*)d_in[6];
    const float* bp   = (const float*)d_in[7];
    const float* Wq   = (const float*)d_in[8];
    const float* bq   = (const float*)d_in[9];
    const float* Wk   = (const float*)d_in[10];
    const float* bk   = (const float*)d_in[11];
    const float* Wvm  = (const float*)d_in[12];
    const float* bvm  = (const float*)d_in[13];
    const float* Wvp  = (const float*)d_in[14];
    const float* bvp  = (const float*)d_in[15];
    const float* We   = (const float*)d_in[16];
    const float* be   = (const float*)d_in[17];
    const float* ds   = (const float*)d_in[18];
    const float* lng  = (const float*)d_in[19];
    const float* lnb  = (const float*)d_in[20];
    const float* rpW  = (const float*)d_in[21];
    const float* rpb  = (const float*)d_in[22];
    const float* h1W  = (const float*)d_in[23];
    const float* h1b  = (const float*)d_in[24];
    const float* h2W  = (const float*)d_in[25];
    const float* h2b  = (const float*)d_in[26];
    float* out = (float*)d_out;

    size_t layer_smem = (size_t)3 * NN * ASTR * sizeof(float);   // 202752
    cudaFuncSetAttribute(k_layer, cudaFuncAttributeMaxDynamicSharedMemorySize, (int)layer_smem);

    k_embed<<<BB, 128>>>(at, sph, Wm, bm, Wp, bp);
    k_prep_m<<<dim3(LL, 4, 4), 256>>>(Wq, Wk);
    k_prep_uv<<<LL, 128>>>(Wq, Wk, bq, bk);
    k_wsplit2<<<2*LL, 256>>>(Wvm, Wvp);

    k_layer<<<BB, 512, layer_smem>>>(ei, ea, We, be, ds, lng, lnb, bvm, bvp);

    k_head<<<BB, 128>>>(rpW, rpb, h1W, h1b, h2W, h2b, out);
}